// round 2
// baseline (speedup 1.0000x reference)
#include <cuda_runtime.h>
#include <math.h>

#define T_LEN  4096
#define HIDDEN 2048
#define QH     16
#define KVH    4
#define HD     128
#define WINDOW 512
#define BQ     16
#define SK     32

// scratch (device globals: no cudaMalloc allowed)
__device__ float g_q[(size_t)T_LEN * QH * HD];
__device__ float g_k[(size_t)T_LEN * KVH * HD];
__device__ float g_v[(size_t)T_LEN * KVH * HD];
__device__ float g_att[(size_t)T_LEN * QH * HD];

// ---------------------------------------------------------------------------
// SGEMM: C[M,N] = A[M,K] * B[N,K]^T  (both row-major; matches w layout [out,in])
// 128x128 block, BK=16, 8x8 per thread, 256 threads.
// M,N multiples of 128; K multiple of 16 (true for all our shapes).
// ---------------------------------------------------------------------------
__global__ __launch_bounds__(256) void sgemm_nt(
    const float* __restrict__ A, const float* __restrict__ B,
    float* __restrict__ C, int M, int N, int K)
{
    __shared__ float As[16][128];
    __shared__ float Bs[16][128];

    const int tid = threadIdx.x;
    const int tx  = tid & 15;   // N direction (8 cols each)
    const int ty  = tid >> 4;   // M direction (8 rows each)

    const float* Ab = A + (size_t)blockIdx.y * 128 * K;
    const float* Bb = B + (size_t)blockIdx.x * 128 * K;

    float acc[8][8];
#pragma unroll
    for (int i = 0; i < 8; ++i)
#pragma unroll
        for (int j = 0; j < 8; ++j) acc[i][j] = 0.f;

    const int lrow = tid >> 2;         // 0..63
    const int lcol = (tid & 3) << 2;   // 0,4,8,12

    for (int k0 = 0; k0 < K; k0 += 16) {
#pragma unroll
        for (int r = 0; r < 2; ++r) {
            int row = lrow + 64 * r;
            float4 a = *reinterpret_cast<const float4*>(Ab + (size_t)row * K + k0 + lcol);
            As[lcol + 0][row] = a.x; As[lcol + 1][row] = a.y;
            As[lcol + 2][row] = a.z; As[lcol + 3][row] = a.w;
            float4 b = *reinterpret_cast<const float4*>(Bb + (size_t)row * K + k0 + lcol);
            Bs[lcol + 0][row] = b.x; Bs[lcol + 1][row] = b.y;
            Bs[lcol + 2][row] = b.z; Bs[lcol + 3][row] = b.w;
        }
        __syncthreads();
#pragma unroll
        for (int k = 0; k < 16; ++k) {
            float a[8], b[8];
            float4 a0 = *reinterpret_cast<const float4*>(&As[k][ty * 8]);
            float4 a1 = *reinterpret_cast<const float4*>(&As[k][ty * 8 + 4]);
            float4 b0 = *reinterpret_cast<const float4*>(&Bs[k][tx * 8]);
            float4 b1 = *reinterpret_cast<const float4*>(&Bs[k][tx * 8 + 4]);
            a[0]=a0.x; a[1]=a0.y; a[2]=a0.z; a[3]=a0.w;
            a[4]=a1.x; a[5]=a1.y; a[6]=a1.z; a[7]=a1.w;
            b[0]=b0.x; b[1]=b0.y; b[2]=b0.z; b[3]=b0.w;
            b[4]=b1.x; b[5]=b1.y; b[6]=b1.z; b[7]=b1.w;
#pragma unroll
            for (int i = 0; i < 8; ++i)
#pragma unroll
                for (int j = 0; j < 8; ++j)
                    acc[i][j] = fmaf(a[i], b[j], acc[i][j]);
        }
        __syncthreads();
    }

    const int crow0 = blockIdx.y * 128 + ty * 8;
    const int ccol0 = blockIdx.x * 128 + tx * 8;
#pragma unroll
    for (int i = 0; i < 8; ++i) {
        float* cr = C + (size_t)(crow0 + i) * N + ccol0;
        float4 v0 = make_float4(acc[i][0], acc[i][1], acc[i][2], acc[i][3]);
        float4 v1 = make_float4(acc[i][4], acc[i][5], acc[i][6], acc[i][7]);
        *reinterpret_cast<float4*>(cr)     = v0;
        *reinterpret_cast<float4*>(cr + 4) = v1;
    }
}

// ---------------------------------------------------------------------------
// RoPE in place: x[t, h, 0:64] / x[t, h, 64:128] rotation, freqs as in ref.
// ---------------------------------------------------------------------------
__global__ void rope_kernel(float* __restrict__ p, int nheads)
{
    int idx = blockIdx.x * blockDim.x + threadIdx.x;
    int total = T_LEN * nheads * (HD / 2);
    if (idx >= total) return;
    int i = idx & 63;
    int h = (idx >> 6) % nheads;
    int t = idx / (64 * nheads);
    float inv = powf(10000.0f, -(float)i / 64.0f);
    float f = (float)t * inv;
    float c = cosf(f), s = sinf(f);
    float* base = p + (size_t)t * nheads * HD + (size_t)h * HD;
    float x1 = base[i];
    float x2 = base[i + 64];
    base[i]      = x1 * c - x2 * s;
    base[i + 64] = x1 * s + x2 * c;
}

// ---------------------------------------------------------------------------
// Windowed causal GQA attention, flash-style streaming softmax.
// Block = (16 queries, 1 q-head). 128 threads; thread owns dim d = tid.
// ---------------------------------------------------------------------------
__global__ __launch_bounds__(128) void attn_kernel(
    const float* __restrict__ Q, const float* __restrict__ Kp,
    const float* __restrict__ V, float* __restrict__ O)
{
    __shared__ float Qs[BQ][HD];         // 8 KB
    __shared__ float Ks[SK][HD + 1];     // padded vs stride-128 conflicts
    __shared__ float Vs[SK][HD + 1];
    __shared__ float Ps[BQ][SK + 1];
    __shared__ float m_s[BQ], l_s[BQ], fac_s[BQ];

    const int tid = threadIdx.x;
    const int h   = blockIdx.y;
    const int g   = h >> 2;              // kv head
    const int qt0 = blockIdx.x * BQ;
    const float scale = 0.08838834764831845f;  // 1/sqrt(128)

    // load Q tile
#pragma unroll
    for (int it = 0; it < 4; ++it) {
        int f4  = tid + it * 128;        // 512 float4s
        int row = f4 >> 5, c4 = f4 & 31;
        float4 qv = *reinterpret_cast<const float4*>(
            Q + (size_t)(qt0 + row) * QH * HD + (size_t)h * HD + c4 * 4);
        *reinterpret_cast<float4*>(&Qs[row][c4 * 4]) = qv;
    }
    if (tid < BQ) { m_s[tid] = -1e30f; l_s[tid] = 0.f; }

    float acc[BQ];
#pragma unroll
    for (int q = 0; q < BQ; ++q) acc[q] = 0.f;
    __syncthreads();

    int s_lo = qt0 - WINDOW; if (s_lo < 0) s_lo = 0;
    const int s_hi = qt0 + BQ - 1;

    for (int s0 = s_lo; s0 <= s_hi; s0 += SK) {
        // load K/V tiles
#pragma unroll
        for (int it = 0; it < (SK * 32) / 128; ++it) {
            int f4  = tid + it * 128;
            int row = f4 >> 5, c4 = f4 & 31;
            int s = s0 + row;
            float4 kv, vv;
            if (s < T_LEN) {
                size_t off = (size_t)s * KVH * HD + (size_t)g * HD + c4 * 4;
                kv = *reinterpret_cast<const float4*>(Kp + off);
                vv = *reinterpret_cast<const float4*>(V + off);
            } else {
                kv = make_float4(0.f, 0.f, 0.f, 0.f);
                vv = kv;
            }
            Ks[row][c4*4+0]=kv.x; Ks[row][c4*4+1]=kv.y; Ks[row][c4*4+2]=kv.z; Ks[row][c4*4+3]=kv.w;
            Vs[row][c4*4+0]=vv.x; Vs[row][c4*4+1]=vv.y; Vs[row][c4*4+2]=vv.z; Vs[row][c4*4+3]=vv.w;
        }
        __syncthreads();

        // scores (512 of them; 4 per thread)
#pragma unroll
        for (int it = 0; it < (BQ * SK) / 128; ++it) {
            int idx = tid + it * 128;
            int q = idx / SK, kk = idx % SK;
            int t = qt0 + q, s = s0 + kk;
            float sc = -1e30f;
            if (s <= t && (t - s) <= WINDOW && s < T_LEN) {
                float dot = 0.f;
#pragma unroll
                for (int d = 0; d < HD; ++d) dot = fmaf(Qs[q][d], Ks[kk][d], dot);
                sc = dot * scale;
            }
            Ps[q][kk] = sc;
        }
        __syncthreads();

        // per-row online softmax update (16 threads)
        if (tid < BQ) {
            int q = tid;
            float m_old = m_s[q];
            float m_new = m_old;
#pragma unroll
            for (int kk = 0; kk < SK; ++kk) m_new = fmaxf(m_new, Ps[q][kk]);
            float f, l;
            if (m_new <= -1e29f) {           // fully masked tile (shouldn't occur)
                f = 1.f; l = l_s[q];
#pragma unroll
                for (int kk = 0; kk < SK; ++kk) Ps[q][kk] = 0.f;
            } else {
                f = __expf(m_old - m_new);
                l = l_s[q] * f;
#pragma unroll
                for (int kk = 0; kk < SK; ++kk) {
                    float p = __expf(Ps[q][kk] - m_new);
                    Ps[q][kk] = p; l += p;
                }
            }
            m_s[q] = m_new; l_s[q] = l; fac_s[q] = f;
        }
        __syncthreads();

        // accumulate PV (thread owns dim d = tid)
#pragma unroll
        for (int q = 0; q < BQ; ++q) {
            float a = acc[q] * fac_s[q];
#pragma unroll
            for (int kk = 0; kk < SK; ++kk) a = fmaf(Ps[q][kk], Vs[kk][tid], a);
            acc[q] = a;
        }
        __syncthreads();
    }

#pragma unroll
    for (int q = 0; q < BQ; ++q) {
        O[(size_t)(qt0 + q) * QH * HD + (size_t)h * HD + tid] = acc[q] / l_s[q];
    }
}

// ---------------------------------------------------------------------------
extern "C" void kernel_launch(void* const* d_in, const int* in_sizes, int n_in,
                              void* d_out, int out_size)
{
    const float* x  = (const float*)d_in[0];
    const float* wq = (const float*)d_in[1];
    const float* wk = (const float*)d_in[2];
    const float* wv = (const float*)d_in[3];
    const float* wo = (const float*)d_in[4];
    float* out = (float*)d_out;

    float *q, *k, *v, *att;
    cudaGetSymbolAddress((void**)&q,   g_q);
    cudaGetSymbolAddress((void**)&k,   g_k);
    cudaGetSymbolAddress((void**)&v,   g_v);
    cudaGetSymbolAddress((void**)&att, g_att);

    // QKV projections
    sgemm_nt<<<dim3((QH * HD) / 128, T_LEN / 128), 256>>>(x, wq, q, T_LEN, QH * HD, HIDDEN);
    sgemm_nt<<<dim3((KVH * HD) / 128, T_LEN / 128), 256>>>(x, wk, k, T_LEN, KVH * HD, HIDDEN);
    sgemm_nt<<<dim3((KVH * HD) / 128, T_LEN / 128), 256>>>(x, wv, v, T_LEN, KVH * HD, HIDDEN);

    // RoPE on q and k
    {
        int totq = T_LEN * QH * (HD / 2);
        rope_kernel<<<(totq + 255) / 256, 256>>>(q, QH);
        int totk = T_LEN * KVH * (HD / 2);
        rope_kernel<<<(totk + 255) / 256, 256>>>(k, KVH);
    }

    // attention
    attn_kernel<<<dim3(T_LEN / BQ, QH), 128>>>(q, k, v, att);

    // output projection
    sgemm_nt<<<dim3(HIDDEN / 128, T_LEN / 128), 256>>>(att, wo, out, T_LEN, HIDDEN, QH * HD);
}

// round 4
// speedup vs baseline: 1.1245x; 1.1245x over previous
#include <cuda_runtime.h>
#include <cuda_bf16.h>
#include <math.h>
#include <stdint.h>

#define T_LEN  4096
#define HIDDEN 2048
#define QH     16
#define KVH    4
#define HD     128
#define WINDOW 512
#define BQ     16
#define SK     32

// ---------------- device scratch (no cudaMalloc allowed) -------------------
__device__ float g_q[(size_t)T_LEN * QH * HD];
__device__ float g_k[(size_t)T_LEN * KVH * HD];
__device__ float g_v[(size_t)T_LEN * KVH * HD];
__device__ float g_att[(size_t)T_LEN * QH * HD];

__device__ __nv_bfloat16 g_xh[(size_t)T_LEN * HIDDEN];
__device__ __nv_bfloat16 g_xl[(size_t)T_LEN * HIDDEN];
__device__ __nv_bfloat16 g_wqh[(size_t)QH * HD * HIDDEN];
__device__ __nv_bfloat16 g_wql[(size_t)QH * HD * HIDDEN];
__device__ __nv_bfloat16 g_wkh[(size_t)KVH * HD * HIDDEN];
__device__ __nv_bfloat16 g_wkl[(size_t)KVH * HD * HIDDEN];
__device__ __nv_bfloat16 g_wvh[(size_t)KVH * HD * HIDDEN];
__device__ __nv_bfloat16 g_wvl[(size_t)KVH * HD * HIDDEN];
__device__ __nv_bfloat16 g_woh[(size_t)HIDDEN * QH * HD];
__device__ __nv_bfloat16 g_wol[(size_t)HIDDEN * QH * HD];
__device__ __nv_bfloat16 g_atth[(size_t)T_LEN * QH * HD];
__device__ __nv_bfloat16 g_attl[(size_t)T_LEN * QH * HD];

// ---------------------------------------------------------------------------
// fp32 -> bf16 hi/lo split (vectorized by 4)
// ---------------------------------------------------------------------------
__global__ void split_kernel(const float* __restrict__ src,
                             __nv_bfloat16* __restrict__ hi,
                             __nv_bfloat16* __restrict__ lo, int n4)
{
    int i = blockIdx.x * blockDim.x + threadIdx.x;
    if (i >= n4) return;
    float4 v = reinterpret_cast<const float4*>(src)[i];
    __nv_bfloat16 h0 = __float2bfloat16(v.x);
    __nv_bfloat16 h1 = __float2bfloat16(v.y);
    __nv_bfloat16 h2 = __float2bfloat16(v.z);
    __nv_bfloat16 h3 = __float2bfloat16(v.w);
    __nv_bfloat16 l0 = __float2bfloat16(v.x - __bfloat162float(h0));
    __nv_bfloat16 l1 = __float2bfloat16(v.y - __bfloat162float(h1));
    __nv_bfloat16 l2 = __float2bfloat16(v.z - __bfloat162float(h2));
    __nv_bfloat16 l3 = __float2bfloat16(v.w - __bfloat162float(h3));
    reinterpret_cast<__nv_bfloat162*>(hi)[2 * i]     = __halves2bfloat162(h0, h1);
    reinterpret_cast<__nv_bfloat162*>(hi)[2 * i + 1] = __halves2bfloat162(h2, h3);
    reinterpret_cast<__nv_bfloat162*>(lo)[2 * i]     = __halves2bfloat162(l0, l1);
    reinterpret_cast<__nv_bfloat162*>(lo)[2 * i + 1] = __halves2bfloat162(l2, l3);
}

// ---------------------------------------------------------------------------
// bf16x3 tensor-core GEMM: C[M,N] = A[M,K] * B[N,K]^T (fp32 accum)
// A,B given as bf16 hi/lo pairs. CTA tile 128x128, BK=32, cp.async 2-stage.
// ---------------------------------------------------------------------------
__device__ __forceinline__ void ldm_x4(uint32_t* r, uint32_t addr)
{
    asm volatile("ldmatrix.sync.aligned.m8n8.x4.shared.b16 {%0,%1,%2,%3}, [%4];\n"
        : "=r"(r[0]), "=r"(r[1]), "=r"(r[2]), "=r"(r[3]) : "r"(addr));
}

__device__ __forceinline__ void mma_bf16(float* d, const uint32_t* a, const uint32_t* b)
{
    asm volatile(
        "mma.sync.aligned.m16n8k16.row.col.f32.bf16.bf16.f32 "
        "{%0,%1,%2,%3}, {%4,%5,%6,%7}, {%8,%9}, {%0,%1,%2,%3};\n"
        : "+f"(d[0]), "+f"(d[1]), "+f"(d[2]), "+f"(d[3])
        : "r"(a[0]), "r"(a[1]), "r"(a[2]), "r"(a[3]), "r"(b[0]), "r"(b[1]));
}

#define GSTAGE 32768  // bytes per stage: 4 arrays * 128 rows * 4 units * 16B

__global__ __launch_bounds__(256) void gemm_bf16x3(
    const __nv_bfloat16* __restrict__ Ah, const __nv_bfloat16* __restrict__ Al,
    const __nv_bfloat16* __restrict__ Bh, const __nv_bfloat16* __restrict__ Bl,
    float* __restrict__ C, int M, int N, int K)
{
    extern __shared__ char smem[];
    const int tid  = threadIdx.x;
    const int lane = tid & 31;
    const int warp = tid >> 5;
    const int wm   = warp >> 2;   // 0..1
    const int wn   = warp & 3;    // 0..3

    const __nv_bfloat16* Abh = Ah + (size_t)blockIdx.y * 128 * K;
    const __nv_bfloat16* Abl = Al + (size_t)blockIdx.y * 128 * K;
    const __nv_bfloat16* Bbh = Bh + (size_t)blockIdx.x * 128 * K;
    const __nv_bfloat16* Bbl = Bl + (size_t)blockIdx.x * 128 * K;

    const uint32_t smem_base = (uint32_t)__cvta_generic_to_shared(smem);

    float acc[4][4][4];
#pragma unroll
    for (int i = 0; i < 4; ++i)
#pragma unroll
        for (int j = 0; j < 4; ++j)
#pragma unroll
            for (int c = 0; c < 4; ++c) acc[i][j][c] = 0.f;

    auto load_stage = [&](int s, int k0) {
#pragma unroll
        for (int i = 0; i < 8; ++i) {
            const __nv_bfloat16* gb = (i < 2) ? Abh : (i < 4) ? Abl : (i < 6) ? Bbh : Bbl;
            int arr = i >> 1;
            int idx = ((i & 1) << 8) + tid;   // 0..511
            int r = idx >> 2, u = idx & 3;
            uint32_t dst = smem_base + s * GSTAGE + arr * 8192 +
                           (((r << 2) + (u ^ ((r >> 1) & 3))) << 4);
            const void* src = gb + (size_t)r * K + k0 + u * 8;
            asm volatile("cp.async.cg.shared.global [%0], [%1], 16;\n" :: "r"(dst), "l"(src));
        }
        asm volatile("cp.async.commit_group;\n");
    };

    const int KT = K >> 5;   // K/32
    load_stage(0, 0);

    for (int kt = 0; kt < KT; ++kt) {
        asm volatile("cp.async.wait_group 0;\n");
        __syncthreads();
        if (kt + 1 < KT) load_stage((kt + 1) & 1, (kt + 1) << 5);

        const uint32_t stA_h = smem_base + (kt & 1) * GSTAGE;
        const uint32_t stA_l = stA_h + 8192;
        const uint32_t stB_h = stA_h + 16384;
        const uint32_t stB_l = stA_h + 24576;

#pragma unroll
        for (int kk = 0; kk < 2; ++kk) {
            const int k0 = kk * 16;
            uint32_t ah[4][4], al[4][4], bh[4][2], bl[4][2];
#pragma unroll
            for (int mt = 0; mt < 4; ++mt) {
                int row = wm * 64 + mt * 16 + ((lane >> 3) & 1) * 8 + (lane & 7);
                int u   = (k0 >> 3) + (lane >> 4);
                uint32_t off = ((row << 2) + (u ^ ((row >> 1) & 3))) << 4;
                ldm_x4(ah[mt], stA_h + off);
                ldm_x4(al[mt], stA_l + off);
            }
#pragma unroll
            for (int p = 0; p < 2; ++p) {
                int row = wn * 32 + p * 16 + ((lane >> 4) & 1) * 8 + (lane & 7);
                int u   = (k0 >> 3) + ((lane >> 3) & 1);
                uint32_t off = ((row << 2) + (u ^ ((row >> 1) & 3))) << 4;
                uint32_t t0[4], t1[4];
                ldm_x4(t0, stB_h + off);
                bh[p * 2][0] = t0[0]; bh[p * 2][1] = t0[1];
                bh[p * 2 + 1][0] = t0[2]; bh[p * 2 + 1][1] = t0[3];
                ldm_x4(t1, stB_l + off);
                bl[p * 2][0] = t1[0]; bl[p * 2][1] = t1[1];
                bl[p * 2 + 1][0] = t1[2]; bl[p * 2 + 1][1] = t1[3];
            }
#pragma unroll
            for (int mt = 0; mt < 4; ++mt)
#pragma unroll
                for (int nt = 0; nt < 4; ++nt) {
                    mma_bf16(acc[mt][nt], ah[mt], bh[nt]);
                    mma_bf16(acc[mt][nt], ah[mt], bl[nt]);
                    mma_bf16(acc[mt][nt], al[mt], bh[nt]);
                }
        }
        __syncthreads();
    }

    const int grp = lane >> 2, tig = lane & 3;
#pragma unroll
    for (int mt = 0; mt < 4; ++mt)
#pragma unroll
        for (int nt = 0; nt < 4; ++nt) {
            int r0 = blockIdx.y * 128 + wm * 64 + mt * 16 + grp;
            int c0 = blockIdx.x * 128 + wn * 32 + nt * 8 + tig * 2;
            float2 v0 = make_float2(acc[mt][nt][0], acc[mt][nt][1]);
            float2 v1 = make_float2(acc[mt][nt][2], acc[mt][nt][3]);
            *reinterpret_cast<float2*>(&C[(size_t)r0 * N + c0])       = v0;
            *reinterpret_cast<float2*>(&C[(size_t)(r0 + 8) * N + c0]) = v1;
        }
}

// ---------------------------------------------------------------------------
// RoPE in place (unchanged)
// ---------------------------------------------------------------------------
__global__ void rope_kernel(float* __restrict__ p, int nheads)
{
    int idx = blockIdx.x * blockDim.x + threadIdx.x;
    int total = T_LEN * nheads * (HD / 2);
    if (idx >= total) return;
    int i = idx & 63;
    int h = (idx >> 6) % nheads;
    int t = idx / (64 * nheads);
    float inv = powf(10000.0f, -(float)i / 64.0f);
    float f = (float)t * inv;
    float c = cosf(f), s = sinf(f);
    float* base = p + (size_t)t * nheads * HD + (size_t)h * HD;
    float x1 = base[i];
    float x2 = base[i + 64];
    base[i]      = x1 * c - x2 * s;
    base[i + 64] = x1 * s + x2 * c;
}

// ---------------------------------------------------------------------------
// Windowed causal GQA attention — restructured for FFMA-bound execution.
// Block = (16 queries, 1 q-head), 128 threads.
// ---------------------------------------------------------------------------
#define HDP (HD + 4)
#define SKP (SK + 4)

__global__ __launch_bounds__(128) void attn_kernel(
    const float* __restrict__ Q, const float* __restrict__ Kp,
    const float* __restrict__ V, float* __restrict__ O)
{
    __shared__ __align__(16) float Qs[BQ][HDP];
    __shared__ __align__(16) float Ks[SK][HDP];
    __shared__ __align__(16) float Vs[SK][HDP];
    __shared__ __align__(16) float Ps[BQ][SKP];
    __shared__ float m_s[BQ], l_s[BQ], fac_s[BQ];

    const int tid = threadIdx.x;
    const int h   = blockIdx.y;
    const int g   = h >> 2;
    const int qt0 = blockIdx.x * BQ;
    const float scale = 0.08838834764831845f;  // 1/sqrt(128)

    // load Q tile
#pragma unroll
    for (int it = 0; it < 4; ++it) {
        int f4  = tid + it * 128;
        int row = f4 >> 5, c4 = f4 & 31;
        float4 qv = *reinterpret_cast<const float4*>(
            Q + (size_t)(qt0 + row) * QH * HD + (size_t)h * HD + c4 * 4);
        *reinterpret_cast<float4*>(&Qs[row][c4 * 4]) = qv;
    }
    if (tid < BQ) { m_s[tid] = -1e30f; l_s[tid] = 0.f; }

    float acc[BQ];
#pragma unroll
    for (int q = 0; q < BQ; ++q) acc[q] = 0.f;
    __syncthreads();

    const int q   = tid >> 3;         // score-phase query row
    const int kk0 = (tid & 7) * 4;    // score-phase key base
    const int t   = qt0 + q;

    int s_lo = qt0 - WINDOW; if (s_lo < 0) s_lo = 0;
    const int s_hi = qt0 + BQ - 1;

    for (int s0 = s_lo; s0 <= s_hi; s0 += SK) {
        // ---- load K/V tiles ----
#pragma unroll
        for (int it = 0; it < (SK * 32) / 128; ++it) {
            int f4  = tid + it * 128;
            int row = f4 >> 5, c4 = f4 & 31;
            int s = s0 + row;
            float4 kv, vv;
            if (s < T_LEN) {
                size_t off = (size_t)s * KVH * HD + (size_t)g * HD + c4 * 4;
                kv = *reinterpret_cast<const float4*>(Kp + off);
                vv = *reinterpret_cast<const float4*>(V + off);
            } else {
                kv = make_float4(0.f, 0.f, 0.f, 0.f);
                vv = kv;
            }
            *reinterpret_cast<float4*>(&Ks[row][c4 * 4]) = kv;
            *reinterpret_cast<float4*>(&Vs[row][c4 * 4]) = vv;
        }
        __syncthreads();

        // ---- scores: thread computes 4 keys for its q ----
        float s4[4] = {0.f, 0.f, 0.f, 0.f};
        {
            const float4* Qp4 = reinterpret_cast<const float4*>(&Qs[q][0]);
            const float4* K0  = reinterpret_cast<const float4*>(&Ks[kk0][0]);
            const float4* K1  = reinterpret_cast<const float4*>(&Ks[kk0 + 1][0]);
            const float4* K2  = reinterpret_cast<const float4*>(&Ks[kk0 + 2][0]);
            const float4* K3  = reinterpret_cast<const float4*>(&Ks[kk0 + 3][0]);
#pragma unroll
            for (int d4 = 0; d4 < HD / 4; ++d4) {
                float4 qv = Qp4[d4];
                float4 k0v = K0[d4], k1v = K1[d4], k2v = K2[d4], k3v = K3[d4];
                s4[0] = fmaf(qv.x, k0v.x, fmaf(qv.y, k0v.y, fmaf(qv.z, k0v.z, fmaf(qv.w, k0v.w, s4[0]))));
                s4[1] = fmaf(qv.x, k1v.x, fmaf(qv.y, k1v.y, fmaf(qv.z, k1v.z, fmaf(qv.w, k1v.w, s4[1]))));
                s4[2] = fmaf(qv.x, k2v.x, fmaf(qv.y, k2v.y, fmaf(qv.z, k2v.z, fmaf(qv.w, k2v.w, s4[2]))));
                s4[3] = fmaf(qv.x, k3v.x, fmaf(qv.y, k3v.y, fmaf(qv.z, k3v.z, fmaf(qv.w, k3v.w, s4[3]))));
            }
        }
#pragma unroll
        for (int j = 0; j < 4; ++j) {
            int s = s0 + kk0 + j;
            bool ok = (s <= t) && (t - s <= WINDOW);
            s4[j] = ok ? s4[j] * scale : -1e30f;
        }

        // ---- warp-parallel online softmax (8 lanes per q-row) ----
        float mloc = fmaxf(fmaxf(s4[0], s4[1]), fmaxf(s4[2], s4[3]));
#pragma unroll
        for (int off = 1; off < 8; off <<= 1)
            mloc = fmaxf(mloc, __shfl_xor_sync(0xffffffffu, mloc, off));
        float m_old = m_s[q];
        float m_new = fmaxf(m_old, mloc);
        float fac   = __expf(m_old - m_new);
        float p0 = __expf(s4[0] - m_new);
        float p1 = __expf(s4[1] - m_new);
        float p2 = __expf(s4[2] - m_new);
        float p3 = __expf(s4[3] - m_new);
        *reinterpret_cast<float4*>(&Ps[q][kk0]) = make_float4(p0, p1, p2, p3);
        float lsum = (p0 + p1) + (p2 + p3);
#pragma unroll
        for (int off = 1; off < 8; off <<= 1)
            lsum += __shfl_xor_sync(0xffffffffu, lsum, off);
        __syncwarp();
        if ((tid & 7) == 0) {
            m_s[q]   = m_new;
            l_s[q]   = l_s[q] * fac + lsum;
            fac_s[q] = fac;
        }
        __syncthreads();

        // ---- PV: thread owns dim d = tid; V column preloaded to regs ----
        float vreg[SK];
#pragma unroll
        for (int kk = 0; kk < SK; ++kk) vreg[kk] = Vs[kk][tid];
#pragma unroll
        for (int qq = 0; qq < BQ; ++qq) {
            float a = acc[qq] * fac_s[qq];
            const float4* Pp = reinterpret_cast<const float4*>(&Ps[qq][0]);
#pragma unroll
            for (int kk4 = 0; kk4 < SK / 4; ++kk4) {
                float4 p = Pp[kk4];
                a = fmaf(p.x, vreg[kk4 * 4 + 0], a);
                a = fmaf(p.y, vreg[kk4 * 4 + 1], a);
                a = fmaf(p.z, vreg[kk4 * 4 + 2], a);
                a = fmaf(p.w, vreg[kk4 * 4 + 3], a);
            }
            acc[qq] = a;
        }
        __syncthreads();
    }

#pragma unroll
    for (int qq = 0; qq < BQ; ++qq) {
        O[(size_t)(qt0 + qq) * QH * HD + (size_t)h * HD + tid] = acc[qq] / l_s[qq];
    }
}

// ---------------------------------------------------------------------------
extern "C" void kernel_launch(void* const* d_in, const int* in_sizes, int n_in,
                              void* d_out, int out_size)
{
    const float* x  = (const float*)d_in[0];
    const float* wq = (const float*)d_in[1];
    const float* wk = (const float*)d_in[2];
    const float* wv = (const float*)d_in[3];
    const float* wo = (const float*)d_in[4];
    float* out = (float*)d_out;

    float *q, *k, *v, *att;
    cudaGetSymbolAddress((void**)&q,   g_q);
    cudaGetSymbolAddress((void**)&k,   g_k);
    cudaGetSymbolAddress((void**)&v,   g_v);
    cudaGetSymbolAddress((void**)&att, g_att);

    __nv_bfloat16 *xh, *xl, *wqh, *wql, *wkh, *wkl, *wvh, *wvl, *woh, *wol, *atth, *attl;
    cudaGetSymbolAddress((void**)&xh,  g_xh);   cudaGetSymbolAddress((void**)&xl,  g_xl);
    cudaGetSymbolAddress((void**)&wqh, g_wqh);  cudaGetSymbolAddress((void**)&wql, g_wql);
    cudaGetSymbolAddress((void**)&wkh, g_wkh);  cudaGetSymbolAddress((void**)&wkl, g_wkl);
    cudaGetSymbolAddress((void**)&wvh, g_wvh);  cudaGetSymbolAddress((void**)&wvl, g_wvl);
    cudaGetSymbolAddress((void**)&woh, g_woh);  cudaGetSymbolAddress((void**)&wol, g_wol);
    cudaGetSymbolAddress((void**)&atth, g_atth); cudaGetSymbolAddress((void**)&attl, g_attl);

    cudaFuncSetAttribute(gemm_bf16x3, cudaFuncAttributeMaxDynamicSharedMemorySize, 2 * GSTAGE);

    // splits
    {
        int n4;
        n4 = T_LEN * HIDDEN / 4;      split_kernel<<<(n4 + 255) / 256, 256>>>(x,  xh,  xl,  n4);
        n4 = QH * HD * HIDDEN / 4;    split_kernel<<<(n4 + 255) / 256, 256>>>(wq, wqh, wql, n4);
        n4 = KVH * HD * HIDDEN / 4;   split_kernel<<<(n4 + 255) / 256, 256>>>(wk, wkh, wkl, n4);
        n4 = KVH * HD * HIDDEN / 4;   split_kernel<<<(n4 + 255) / 256, 256>>>(wv, wvh, wvl, n4);
        n4 = HIDDEN * QH * HD / 4;    split_kernel<<<(n4 + 255) / 256, 256>>>(wo, woh, wol, n4);
    }

    // QKV projections (bf16x3 tensor GEMM)
    gemm_bf16x3<<<dim3((QH * HD) / 128,  T_LEN / 128), 256, 2 * GSTAGE>>>(
        xh, xl, wqh, wql, q, T_LEN, QH * HD, HIDDEN);
    gemm_bf16x3<<<dim3((KVH * HD) / 128, T_LEN / 128), 256, 2 * GSTAGE>>>(
        xh, xl, wkh, wkl, k, T_LEN, KVH * HD, HIDDEN);
    gemm_bf16x3<<<dim3((KVH * HD) / 128, T_LEN / 128), 256, 2 * GSTAGE>>>(
        xh, xl, wvh, wvl, v, T_LEN, KVH * HD, HIDDEN);

    // RoPE
    {
        int totq = T_LEN * QH * (HD / 2);
        rope_kernel<<<(totq + 255) / 256, 256>>>(q, QH);
        int totk = T_LEN * KVH * (HD / 2);
        rope_kernel<<<(totk + 255) / 256, 256>>>(k, KVH);
    }

    // attention
    attn_kernel<<<dim3(T_LEN / BQ, QH), 128>>>(q, k, v, att);

    // output projection
    {
        int n4 = T_LEN * QH * HD / 4;
        split_kernel<<<(n4 + 255) / 256, 256>>>(att, atth, attl, n4);
    }
    gemm_bf16x3<<<dim3(HIDDEN / 128, T_LEN / 128), 256, 2 * GSTAGE>>>(
        atth, attl, woh, wol, out, T_LEN, HIDDEN, QH * HD);
}

// round 7
// speedup vs baseline: 3.6062x; 3.2070x over previous
#include <cuda_runtime.h>
#include <cuda_bf16.h>
#include <math.h>
#include <stdint.h>

#define T_LEN  4096
#define HIDDEN 2048
#define QH     16
#define KVH    4
#define HD     128
#define WINDOW 512

// ---------------- device scratch (no cudaMalloc allowed) -------------------
__device__ float g_q[(size_t)T_LEN * QH * HD];
__device__ float g_k[(size_t)T_LEN * KVH * HD];
__device__ float g_v[(size_t)T_LEN * KVH * HD];

__device__ __nv_bfloat16 g_xh[(size_t)T_LEN * HIDDEN];
__device__ __nv_bfloat16 g_xl[(size_t)T_LEN * HIDDEN];
__device__ __nv_bfloat16 g_wqh[(size_t)QH * HD * HIDDEN];
__device__ __nv_bfloat16 g_wql[(size_t)QH * HD * HIDDEN];
__device__ __nv_bfloat16 g_wkh[(size_t)KVH * HD * HIDDEN];
__device__ __nv_bfloat16 g_wkl[(size_t)KVH * HD * HIDDEN];
__device__ __nv_bfloat16 g_wvh[(size_t)KVH * HD * HIDDEN];
__device__ __nv_bfloat16 g_wvl[(size_t)KVH * HD * HIDDEN];
__device__ __nv_bfloat16 g_woh[(size_t)HIDDEN * QH * HD];
__device__ __nv_bfloat16 g_wol[(size_t)HIDDEN * QH * HD];

__device__ __nv_bfloat16 g_qh[(size_t)T_LEN * QH * HD];
__device__ __nv_bfloat16 g_ql[(size_t)T_LEN * QH * HD];
__device__ __nv_bfloat16 g_kh[(size_t)T_LEN * KVH * HD];
__device__ __nv_bfloat16 g_kl[(size_t)T_LEN * KVH * HD];
__device__ __nv_bfloat16 g_vh[(size_t)T_LEN * KVH * HD];
__device__ __nv_bfloat16 g_vl[(size_t)T_LEN * KVH * HD];
__device__ __nv_bfloat16 g_atth[(size_t)T_LEN * QH * HD];
__device__ __nv_bfloat16 g_attl[(size_t)T_LEN * QH * HD];

// ---------------------------------------------------------------------------
// helpers
// ---------------------------------------------------------------------------
__device__ __forceinline__ void ldm_x4(uint32_t* r, uint32_t addr)
{
    asm volatile("ldmatrix.sync.aligned.m8n8.x4.shared.b16 {%0,%1,%2,%3}, [%4];\n"
        : "=r"(r[0]), "=r"(r[1]), "=r"(r[2]), "=r"(r[3]) : "r"(addr));
}
__device__ __forceinline__ void ldm_x4_t(uint32_t* r, uint32_t addr)
{
    asm volatile("ldmatrix.sync.aligned.m8n8.x4.trans.shared.b16 {%0,%1,%2,%3}, [%4];\n"
        : "=r"(r[0]), "=r"(r[1]), "=r"(r[2]), "=r"(r[3]) : "r"(addr));
}
__device__ __forceinline__ void mma_bf16(float* d, const uint32_t* a, const uint32_t* b)
{
    asm volatile(
        "mma.sync.aligned.m16n8k16.row.col.f32.bf16.bf16.f32 "
        "{%0,%1,%2,%3}, {%4,%5,%6,%7}, {%8,%9}, {%0,%1,%2,%3};\n"
        : "+f"(d[0]), "+f"(d[1]), "+f"(d[2]), "+f"(d[3])
        : "r"(a[0]), "r"(a[1]), "r"(a[2]), "r"(a[3]), "r"(b[0]), "r"(b[1]));
}
__device__ __forceinline__ void pack_hilo(float a, float b, uint32_t& hi, uint32_t& lo)
{
    __nv_bfloat16 ha = __float2bfloat16(a);
    __nv_bfloat16 hb = __float2bfloat16(b);
    __nv_bfloat162 h2 = __halves2bfloat162(ha, hb);
    __nv_bfloat162 l2 = __halves2bfloat162(__float2bfloat16(a - __bfloat162float(ha)),
                                           __float2bfloat16(b - __bfloat162float(hb)));
    hi = *reinterpret_cast<uint32_t*>(&h2);
    lo = *reinterpret_cast<uint32_t*>(&l2);
}

// ---------------------------------------------------------------------------
// fp32 -> bf16 hi/lo split (vectorized by 4)
// ---------------------------------------------------------------------------
__global__ void split_kernel(const float* __restrict__ src,
                             __nv_bfloat16* __restrict__ hi,
                             __nv_bfloat16* __restrict__ lo, int n4)
{
    int i = blockIdx.x * blockDim.x + threadIdx.x;
    if (i >= n4) return;
    float4 v = reinterpret_cast<const float4*>(src)[i];
    __nv_bfloat16 h0 = __float2bfloat16(v.x);
    __nv_bfloat16 h1 = __float2bfloat16(v.y);
    __nv_bfloat16 h2 = __float2bfloat16(v.z);
    __nv_bfloat16 h3 = __float2bfloat16(v.w);
    __nv_bfloat16 l0 = __float2bfloat16(v.x - __bfloat162float(h0));
    __nv_bfloat16 l1 = __float2bfloat16(v.y - __bfloat162float(h1));
    __nv_bfloat16 l2 = __float2bfloat16(v.z - __bfloat162float(h2));
    __nv_bfloat16 l3 = __float2bfloat16(v.w - __bfloat162float(h3));
    reinterpret_cast<__nv_bfloat162*>(hi)[2 * i]     = __halves2bfloat162(h0, h1);
    reinterpret_cast<__nv_bfloat162*>(hi)[2 * i + 1] = __halves2bfloat162(h2, h3);
    reinterpret_cast<__nv_bfloat162*>(lo)[2 * i]     = __halves2bfloat162(l0, l1);
    reinterpret_cast<__nv_bfloat162*>(lo)[2 * i + 1] = __halves2bfloat162(l2, l3);
}

// ---------------------------------------------------------------------------
// RoPE (fp32) + hi/lo split, with optional pre-scaling (for Q: 1/sqrt(HD))
// ---------------------------------------------------------------------------
__global__ void rope_split_kernel(const float* __restrict__ src,
                                  __nv_bfloat16* __restrict__ hi,
                                  __nv_bfloat16* __restrict__ lo,
                                  int nheads, float scale)
{
    int idx = blockIdx.x * blockDim.x + threadIdx.x;
    int total = T_LEN * nheads * (HD / 2);
    if (idx >= total) return;
    int i = idx & 63;
    int h = (idx >> 6) % nheads;
    int t = idx / (64 * nheads);
    float inv = powf(10000.0f, -(float)i / 64.0f);
    float f = (float)t * inv;
    float c = cosf(f), s = sinf(f);
    size_t base = (size_t)t * nheads * HD + (size_t)h * HD;
    float x1 = src[base + i];
    float x2 = src[base + i + 64];
    float y1 = (x1 * c - x2 * s) * scale;
    float y2 = (x1 * s + x2 * c) * scale;
    __nv_bfloat16 h1 = __float2bfloat16(y1);
    __nv_bfloat16 h2 = __float2bfloat16(y2);
    hi[base + i]      = h1;
    hi[base + i + 64] = h2;
    lo[base + i]      = __float2bfloat16(y1 - __bfloat162float(h1));
    lo[base + i + 64] = __float2bfloat16(y2 - __bfloat162float(h2));
}

// ---------------------------------------------------------------------------
// bf16x3 tensor-core GEMM: C[M,N] = A[M,K] * B[N,K]^T (fp32 accum)
// ---------------------------------------------------------------------------
#define GSTAGE 32768

__global__ __launch_bounds__(256) void gemm_bf16x3(
    const __nv_bfloat16* __restrict__ Ah, const __nv_bfloat16* __restrict__ Al,
    const __nv_bfloat16* __restrict__ Bh, const __nv_bfloat16* __restrict__ Bl,
    float* __restrict__ C, int M, int N, int K)
{
    extern __shared__ char smem[];
    const int tid  = threadIdx.x;
    const int lane = tid & 31;
    const int warp = tid >> 5;
    const int wm   = warp >> 2;
    const int wn   = warp & 3;

    const __nv_bfloat16* Abh = Ah + (size_t)blockIdx.y * 128 * K;
    const __nv_bfloat16* Abl = Al + (size_t)blockIdx.y * 128 * K;
    const __nv_bfloat16* Bbh = Bh + (size_t)blockIdx.x * 128 * K;
    const __nv_bfloat16* Bbl = Bl + (size_t)blockIdx.x * 128 * K;

    const uint32_t smem_base = (uint32_t)__cvta_generic_to_shared(smem);

    float acc[4][4][4];
#pragma unroll
    for (int i = 0; i < 4; ++i)
#pragma unroll
        for (int j = 0; j < 4; ++j)
#pragma unroll
            for (int c = 0; c < 4; ++c) acc[i][j][c] = 0.f;

    auto load_stage = [&](int s, int k0) {
#pragma unroll
        for (int i = 0; i < 8; ++i) {
            const __nv_bfloat16* gb = (i < 2) ? Abh : (i < 4) ? Abl : (i < 6) ? Bbh : Bbl;
            int arr = i >> 1;
            int idx = ((i & 1) << 8) + tid;
            int r = idx >> 2, u = idx & 3;
            uint32_t dst = smem_base + s * GSTAGE + arr * 8192 +
                           (((r << 2) + (u ^ ((r >> 1) & 3))) << 4);
            const void* src = gb + (size_t)r * K + k0 + u * 8;
            asm volatile("cp.async.cg.shared.global [%0], [%1], 16;\n" :: "r"(dst), "l"(src));
        }
        asm volatile("cp.async.commit_group;\n");
    };

    const int KT = K >> 5;
    load_stage(0, 0);

    for (int kt = 0; kt < KT; ++kt) {
        asm volatile("cp.async.wait_group 0;\n");
        __syncthreads();
        if (kt + 1 < KT) load_stage((kt + 1) & 1, (kt + 1) << 5);

        const uint32_t stA_h = smem_base + (kt & 1) * GSTAGE;
        const uint32_t stA_l = stA_h + 8192;
        const uint32_t stB_h = stA_h + 16384;
        const uint32_t stB_l = stA_h + 24576;

#pragma unroll
        for (int kk = 0; kk < 2; ++kk) {
            const int k0 = kk * 16;
            uint32_t ah[4][4], al[4][4], bh[4][2], bl[4][2];
#pragma unroll
            for (int mt = 0; mt < 4; ++mt) {
                int row = wm * 64 + mt * 16 + ((lane >> 3) & 1) * 8 + (lane & 7);
                int u   = (k0 >> 3) + (lane >> 4);
                uint32_t off = ((row << 2) + (u ^ ((row >> 1) & 3))) << 4;
                ldm_x4(ah[mt], stA_h + off);
                ldm_x4(al[mt], stA_l + off);
            }
#pragma unroll
            for (int p = 0; p < 2; ++p) {
                int row = wn * 32 + p * 16 + ((lane >> 4) & 1) * 8 + (lane & 7);
                int u   = (k0 >> 3) + ((lane >> 3) & 1);
                uint32_t off = ((row << 2) + (u ^ ((row >> 1) & 3))) << 4;
                uint32_t t0[4], t1[4];
                ldm_x4(t0, stB_h + off);
                bh[p * 2][0] = t0[0]; bh[p * 2][1] = t0[1];
                bh[p * 2 + 1][0] = t0[2]; bh[p * 2 + 1][1] = t0[3];
                ldm_x4(t1, stB_l + off);
                bl[p * 2][0] = t1[0]; bl[p * 2][1] = t1[1];
                bl[p * 2 + 1][0] = t1[2]; bl[p * 2 + 1][1] = t1[3];
            }
#pragma unroll
            for (int mt = 0; mt < 4; ++mt)
#pragma unroll
                for (int nt = 0; nt < 4; ++nt) {
                    mma_bf16(acc[mt][nt], ah[mt], bh[nt]);
                    mma_bf16(acc[mt][nt], ah[mt], bl[nt]);
                    mma_bf16(acc[mt][nt], al[mt], bh[nt]);
                }
        }
        __syncthreads();
    }

    const int grp = lane >> 2, tig = lane & 3;
#pragma unroll
    for (int mt = 0; mt < 4; ++mt)
#pragma unroll
        for (int nt = 0; nt < 4; ++nt) {
            int r0 = blockIdx.y * 128 + wm * 64 + mt * 16 + grp;
            int c0 = blockIdx.x * 128 + wn * 32 + nt * 8 + tig * 2;
            float2 v0 = make_float2(acc[mt][nt][0], acc[mt][nt][1]);
            float2 v1 = make_float2(acc[mt][nt][2], acc[mt][nt][3]);
            *reinterpret_cast<float2*>(&C[(size_t)r0 * N + c0])       = v0;
            *reinterpret_cast<float2*>(&C[(size_t)(r0 + 8) * N + c0]) = v1;
        }
}

// ---------------------------------------------------------------------------
// Tensor-core flash attention (bf16x3 for QK^T and PV).
// CTA: 64 queries x 1 head, 4 warps. SK=32 keys per iter, double-buffered.
// smem stage (32KB): Kh @0, Kl @8192, Vh @16384, Vl @24576; rows of 256B,
// 16B-unit swizzle u^(r&7).
// ---------------------------------------------------------------------------
#define AT_STAGE 32768

__global__ __launch_bounds__(128) void attn_mma(
    const __nv_bfloat16* __restrict__ Qh, const __nv_bfloat16* __restrict__ Ql,
    const __nv_bfloat16* __restrict__ Kh, const __nv_bfloat16* __restrict__ Kl,
    const __nv_bfloat16* __restrict__ Vh, const __nv_bfloat16* __restrict__ Vl,
    __nv_bfloat16* __restrict__ Oh, __nv_bfloat16* __restrict__ Ol)
{
    extern __shared__ char smem[];
    const uint32_t sb = (uint32_t)__cvta_generic_to_shared(smem);
    const int tid = threadIdx.x, lane = tid & 31, w = tid >> 5;
    const int h = blockIdx.y, g = h >> 2;
    const int qt0 = blockIdx.x * 64;
    const int grp = lane >> 2, tig = lane & 3;
    const int row0 = qt0 + w * 16 + grp;      // rows row0, row0+8

    // ---- Q fragments (hi/lo), scale pre-folded upstream ----
    uint32_t qfh[8][4], qfl[8][4];
#pragma unroll
    for (int c = 0; c < 8; ++c) {
        int d0 = 16 * c + 2 * tig;
        size_t b0 = ((size_t)row0 * QH + h) * HD;
        size_t b1 = ((size_t)(row0 + 8) * QH + h) * HD;
        qfh[c][0] = *reinterpret_cast<const uint32_t*>(Qh + b0 + d0);
        qfh[c][1] = *reinterpret_cast<const uint32_t*>(Qh + b1 + d0);
        qfh[c][2] = *reinterpret_cast<const uint32_t*>(Qh + b0 + d0 + 8);
        qfh[c][3] = *reinterpret_cast<const uint32_t*>(Qh + b1 + d0 + 8);
        qfl[c][0] = *reinterpret_cast<const uint32_t*>(Ql + b0 + d0);
        qfl[c][1] = *reinterpret_cast<const uint32_t*>(Ql + b1 + d0);
        qfl[c][2] = *reinterpret_cast<const uint32_t*>(Ql + b0 + d0 + 8);
        qfl[c][3] = *reinterpret_cast<const uint32_t*>(Ql + b1 + d0 + 8);
    }

    float o[16][4];
#pragma unroll
    for (int n = 0; n < 16; ++n)
#pragma unroll
        for (int j = 0; j < 4; ++j) o[n][j] = 0.f;
    float m0 = -1e30f, m1 = -1e30f, l0 = 0.f, l1 = 0.f;

    int s_lo = qt0 - WINDOW; if (s_lo < 0) s_lo = 0;
    const int n_tiles = (qt0 + 64 - s_lo) / 32;

    auto load_stage = [&](int st, int s0) {
#pragma unroll
        for (int j = 0; j < 16; ++j) {
            int i = tid + 128 * j;
            int arr = i >> 9;
            int rem = i & 511;
            int r = rem >> 4, u = rem & 15;
            const __nv_bfloat16* gp =
                (arr == 0 ? Kh : arr == 1 ? Kl : arr == 2 ? Vh : Vl) +
                ((size_t)(s0 + r) * KVH + g) * HD + u * 8;
            uint32_t dst = sb + st * AT_STAGE + arr * 8192 + r * 256 + ((u ^ (r & 7)) << 4);
            asm volatile("cp.async.cg.shared.global [%0], [%1], 16;\n" :: "r"(dst), "l"(gp));
        }
        asm volatile("cp.async.commit_group;\n");
    };

    load_stage(0, s_lo);

    for (int tile = 0; tile < n_tiles; ++tile) {
        const int s0 = s_lo + tile * 32;
        if (tile + 1 < n_tiles) {
            load_stage((tile + 1) & 1, s0 + 32);
            asm volatile("cp.async.wait_group 1;\n");
        } else {
            asm volatile("cp.async.wait_group 0;\n");
        }
        __syncthreads();

        const uint32_t st = sb + (tile & 1) * AT_STAGE;

        // ---- S = Qscaled . K^T  (bf16x3) ----
        float S[4][4];
#pragma unroll
        for (int n = 0; n < 4; ++n)
#pragma unroll
            for (int j = 0; j < 4; ++j) S[n][j] = 0.f;

#pragma unroll
        for (int c = 0; c < 8; ++c) {
            uint32_t kh[2][4], kl[2][4];
#pragma unroll
            for (int p = 0; p < 2; ++p) {
                int row = p * 16 + (lane & 7) + 8 * ((lane >> 3) & 1);
                int u   = 2 * c + (lane >> 4);
                uint32_t off = row * 256 + ((u ^ (row & 7)) << 4);
                ldm_x4(kh[p], st + off);
                ldm_x4(kl[p], st + 8192 + off);
            }
#pragma unroll
            for (int n = 0; n < 4; ++n) {
                uint32_t bh[2] = { kh[n >> 1][n & 1], kh[n >> 1][(n & 1) + 2] };
                uint32_t bl[2] = { kl[n >> 1][n & 1], kl[n >> 1][(n & 1) + 2] };
                mma_bf16(S[n], qfh[c], bh);
                mma_bf16(S[n], qfh[c], bl);
                mma_bf16(S[n], qfl[c], bh);
            }
        }

        // ---- masking ----
        bool causal_safe = (s0 + 31 <= qt0 + 16 * w);
        bool window_safe = (s0 >= qt0 + 16 * w + 15 - WINDOW);
        if (!(causal_safe && window_safe)) {
#pragma unroll
            for (int n = 0; n < 4; ++n)
#pragma unroll
                for (int j = 0; j < 4; ++j) {
                    int s = s0 + 8 * n + 2 * tig + (j & 1);
                    int t = (j < 2) ? row0 : row0 + 8;
                    bool ok = (s <= t) && (t - s <= WINDOW);
                    if (!ok) S[n][j] = -1e30f;
                }
        }

        // ---- online softmax ----
        float mx0 = -1e30f, mx1 = -1e30f;
#pragma unroll
        for (int n = 0; n < 4; ++n) {
            mx0 = fmaxf(mx0, fmaxf(S[n][0], S[n][1]));
            mx1 = fmaxf(mx1, fmaxf(S[n][2], S[n][3]));
        }
        mx0 = fmaxf(mx0, __shfl_xor_sync(0xffffffffu, mx0, 1));
        mx0 = fmaxf(mx0, __shfl_xor_sync(0xffffffffu, mx0, 2));
        mx1 = fmaxf(mx1, __shfl_xor_sync(0xffffffffu, mx1, 1));
        mx1 = fmaxf(mx1, __shfl_xor_sync(0xffffffffu, mx1, 2));

        float mn0 = fmaxf(m0, mx0), mn1 = fmaxf(m1, mx1);
        float fac0 = __expf(m0 - mn0), fac1 = __expf(m1 - mn1);
        m0 = mn0; m1 = mn1;

        float rs0 = 0.f, rs1 = 0.f;
#pragma unroll
        for (int n = 0; n < 4; ++n) {
            S[n][0] = __expf(S[n][0] - mn0);
            S[n][1] = __expf(S[n][1] - mn0);
            S[n][2] = __expf(S[n][2] - mn1);
            S[n][3] = __expf(S[n][3] - mn1);
            rs0 += S[n][0] + S[n][1];
            rs1 += S[n][2] + S[n][3];
        }
        rs0 += __shfl_xor_sync(0xffffffffu, rs0, 1);
        rs0 += __shfl_xor_sync(0xffffffffu, rs0, 2);
        rs1 += __shfl_xor_sync(0xffffffffu, rs1, 1);
        rs1 += __shfl_xor_sync(0xffffffffu, rs1, 2);
        l0 = l0 * fac0 + rs0;
        l1 = l1 * fac1 + rs1;

#pragma unroll
        for (int n = 0; n < 16; ++n) {
            o[n][0] *= fac0; o[n][1] *= fac0;
            o[n][2] *= fac1; o[n][3] *= fac1;
        }

        // ---- O += P . V  (bf16x3) ----
#pragma unroll
        for (int kc = 0; kc < 2; ++kc) {
            int j0 = 2 * kc, j1 = 2 * kc + 1;
            uint32_t pah[4], pal[4];
            pack_hilo(S[j0][0], S[j0][1], pah[0], pal[0]);
            pack_hilo(S[j0][2], S[j0][3], pah[1], pal[1]);
            pack_hilo(S[j1][0], S[j1][1], pah[2], pal[2]);
            pack_hilo(S[j1][2], S[j1][3], pah[3], pal[3]);
#pragma unroll
            for (int dp = 0; dp < 8; ++dp) {
                int row = kc * 16 + (lane & 7) + 8 * ((lane >> 3) & 1);
                int u   = 2 * dp + (lane >> 4);
                uint32_t off = row * 256 + ((u ^ (row & 7)) << 4);
                uint32_t vh[4], vl[4];
                ldm_x4_t(vh, st + 16384 + off);
                ldm_x4_t(vl, st + 24576 + off);
                uint32_t bh0[2] = { vh[0], vh[1] }, bh1[2] = { vh[2], vh[3] };
                uint32_t bl0[2] = { vl[0], vl[1] }, bl1[2] = { vl[2], vl[3] };
                mma_bf16(o[2 * dp],     pah, bh0);
                mma_bf16(o[2 * dp],     pah, bl0);
                mma_bf16(o[2 * dp],     pal, bh0);
                mma_bf16(o[2 * dp + 1], pah, bh1);
                mma_bf16(o[2 * dp + 1], pah, bl1);
                mma_bf16(o[2 * dp + 1], pal, bh1);
            }
        }
        __syncthreads();
    }

    // ---- epilogue: normalize, hi/lo split, store ----
    float inv0 = 1.0f / l0, inv1 = 1.0f / l1;
#pragma unroll
    for (int n = 0; n < 16; ++n) {
        int d = 8 * n + 2 * tig;
        float a0 = o[n][0] * inv0, a1 = o[n][1] * inv0;
        float b0 = o[n][2] * inv1, b1 = o[n][3] * inv1;
        uint32_t h0, lo0, h1, lo1;
        pack_hilo(a0, a1, h0, lo0);
        pack_hilo(b0, b1, h1, lo1);
        size_t p0 = ((size_t)row0 * QH + h) * HD + d;
        size_t p1 = ((size_t)(row0 + 8) * QH + h) * HD + d;
        *reinterpret_cast<uint32_t*>(Oh + p0) = h0;
        *reinterpret_cast<uint32_t*>(Ol + p0) = lo0;
        *reinterpret_cast<uint32_t*>(Oh + p1) = h1;
        *reinterpret_cast<uint32_t*>(Ol + p1) = lo1;
    }
}

// ---------------------------------------------------------------------------
extern "C" void kernel_launch(void* const* d_in, const int* in_sizes, int n_in,
                              void* d_out, int out_size)
{
    const float* x  = (const float*)d_in[0];
    const float* wq = (const float*)d_in[1];
    const float* wk = (const float*)d_in[2];
    const float* wv = (const float*)d_in[3];
    const float* wo = (const float*)d_in[4];
    float* out = (float*)d_out;

    float *q, *k, *v;
    cudaGetSymbolAddress((void**)&q, g_q);
    cudaGetSymbolAddress((void**)&k, g_k);
    cudaGetSymbolAddress((void**)&v, g_v);

    __nv_bfloat16 *xh, *xl, *wqh, *wql, *wkh, *wkl, *wvh, *wvl, *woh, *wol;
    __nv_bfloat16 *qh, *ql, *kh, *kl, *vh, *vl, *atth, *attl;
    cudaGetSymbolAddress((void**)&xh,  g_xh);   cudaGetSymbolAddress((void**)&xl,  g_xl);
    cudaGetSymbolAddress((void**)&wqh, g_wqh);  cudaGetSymbolAddress((void**)&wql, g_wql);
    cudaGetSymbolAddress((void**)&wkh, g_wkh);  cudaGetSymbolAddress((void**)&wkl, g_wkl);
    cudaGetSymbolAddress((void**)&wvh, g_wvh);  cudaGetSymbolAddress((void**)&wvl, g_wvl);
    cudaGetSymbolAddress((void**)&woh, g_woh);  cudaGetSymbolAddress((void**)&wol, g_wol);
    cudaGetSymbolAddress((void**)&qh,  g_qh);   cudaGetSymbolAddress((void**)&ql,  g_ql);
    cudaGetSymbolAddress((void**)&kh,  g_kh);   cudaGetSymbolAddress((void**)&kl,  g_kl);
    cudaGetSymbolAddress((void**)&vh,  g_vh);   cudaGetSymbolAddress((void**)&vl,  g_vl);
    cudaGetSymbolAddress((void**)&atth, g_atth); cudaGetSymbolAddress((void**)&attl, g_attl);

    cudaFuncSetAttribute(gemm_bf16x3, cudaFuncAttributeMaxDynamicSharedMemorySize, 2 * GSTAGE);
    cudaFuncSetAttribute(attn_mma,    cudaFuncAttributeMaxDynamicSharedMemorySize, 2 * AT_STAGE);

    // input / weight splits
    {
        int n4;
        n4 = T_LEN * HIDDEN / 4;      split_kernel<<<(n4 + 255) / 256, 256>>>(x,  xh,  xl,  n4);
        n4 = QH * HD * HIDDEN / 4;    split_kernel<<<(n4 + 255) / 256, 256>>>(wq, wqh, wql, n4);
        n4 = KVH * HD * HIDDEN / 4;   split_kernel<<<(n4 + 255) / 256, 256>>>(wk, wkh, wkl, n4);
        n4 = KVH * HD * HIDDEN / 4;   split_kernel<<<(n4 + 255) / 256, 256>>>(wv, wvh, wvl, n4);
        n4 = HIDDEN * QH * HD / 4;    split_kernel<<<(n4 + 255) / 256, 256>>>(wo, woh, wol, n4);
    }

    // QKV projections
    gemm_bf16x3<<<dim3((QH * HD) / 128,  T_LEN / 128), 256, 2 * GSTAGE>>>(
        xh, xl, wqh, wql, q, T_LEN, QH * HD, HIDDEN);
    gemm_bf16x3<<<dim3((KVH * HD) / 128, T_LEN / 128), 256, 2 * GSTAGE>>>(
        xh, xl, wkh, wkl, k, T_LEN, KVH * HD, HIDDEN);
    gemm_bf16x3<<<dim3((KVH * HD) / 128, T_LEN / 128), 256, 2 * GSTAGE>>>(
        xh, xl, wvh, wvl, v, T_LEN, KVH * HD, HIDDEN);

    // RoPE + split (scale folded into Q), V split
    {
        const float scale = 0.08838834764831845f;  // 1/sqrt(128)
        int totq = T_LEN * QH * (HD / 2);
        rope_split_kernel<<<(totq + 255) / 256, 256>>>(q, qh, ql, QH, scale);
        int totk = T_LEN * KVH * (HD / 2);
        rope_split_kernel<<<(totk + 255) / 256, 256>>>(k, kh, kl, KVH, 1.0f);
        int n4 = T_LEN * KVH * HD / 4;
        split_kernel<<<(n4 + 255) / 256, 256>>>(v, vh, vl, n4);
    }

    // tensor-core attention -> writes hi/lo bf16 directly
    attn_mma<<<dim3(T_LEN / 64, QH), 128, 2 * AT_STAGE>>>(
        qh, ql, kh, kl, vh, vl, atth, attl);

    // output projection
    gemm_bf16x3<<<dim3(HIDDEN / 128, T_LEN / 128), 256, 2 * GSTAGE>>>(
        atth, attl, woh, wol, out, T_LEN, HIDDEN, QH * HD);
}

// round 13
// speedup vs baseline: 4.0679x; 1.1280x over previous
#include <cuda_runtime.h>
#include <cuda_bf16.h>
#include <math.h>
#include <stdint.h>

#define T_LEN  4096
#define HIDDEN 2048
#define QH     16
#define KVH    4
#define HD     128
#define WINDOW 512
#define NC     3072   // fused QKV output width: 2048 + 512 + 512

// ---------------- device scratch (no cudaMalloc allowed) -------------------
__device__ float g_qkv[(size_t)T_LEN * NC];

__device__ __nv_bfloat16 g_xh[(size_t)T_LEN * HIDDEN];
__device__ __nv_bfloat16 g_xl[(size_t)T_LEN * HIDDEN];
__device__ __nv_bfloat16 g_wch[(size_t)NC * HIDDEN];     // concat wq|wk|wv hi
__device__ __nv_bfloat16 g_wcl[(size_t)NC * HIDDEN];     // concat wq|wk|wv lo
__device__ __nv_bfloat16 g_woh[(size_t)HIDDEN * QH * HD];
__device__ __nv_bfloat16 g_wol[(size_t)HIDDEN * QH * HD];

__device__ __nv_bfloat16 g_qh[(size_t)T_LEN * QH * HD];
__device__ __nv_bfloat16 g_ql[(size_t)T_LEN * QH * HD];
__device__ __nv_bfloat16 g_kh[(size_t)T_LEN * KVH * HD];
__device__ __nv_bfloat16 g_kl[(size_t)T_LEN * KVH * HD];
__device__ __nv_bfloat16 g_vh[(size_t)T_LEN * KVH * HD];
__device__ __nv_bfloat16 g_vl[(size_t)T_LEN * KVH * HD];
__device__ __nv_bfloat16 g_atth[(size_t)T_LEN * QH * HD];
__device__ __nv_bfloat16 g_attl[(size_t)T_LEN * QH * HD];

// ---------------------------------------------------------------------------
// helpers
// ---------------------------------------------------------------------------
__device__ __forceinline__ void ldm_x4(uint32_t* r, uint32_t addr)
{
    asm volatile("ldmatrix.sync.aligned.m8n8.x4.shared.b16 {%0,%1,%2,%3}, [%4];\n"
        : "=r"(r[0]), "=r"(r[1]), "=r"(r[2]), "=r"(r[3]) : "r"(addr));
}
__device__ __forceinline__ void ldm_x4_t(uint32_t* r, uint32_t addr)
{
    asm volatile("ldmatrix.sync.aligned.m8n8.x4.trans.shared.b16 {%0,%1,%2,%3}, [%4];\n"
        : "=r"(r[0]), "=r"(r[1]), "=r"(r[2]), "=r"(r[3]) : "r"(addr));
}
__device__ __forceinline__ void mma_bf16(float* d, const uint32_t* a, const uint32_t* b)
{
    asm volatile(
        "mma.sync.aligned.m16n8k16.row.col.f32.bf16.bf16.f32 "
        "{%0,%1,%2,%3}, {%4,%5,%6,%7}, {%8,%9}, {%0,%1,%2,%3};\n"
        : "+f"(d[0]), "+f"(d[1]), "+f"(d[2]), "+f"(d[3])
        : "r"(a[0]), "r"(a[1]), "r"(a[2]), "r"(a[3]), "r"(b[0]), "r"(b[1]));
}
__device__ __forceinline__ void pack_hilo(float a, float b, uint32_t& hi, uint32_t& lo)
{
    __nv_bfloat16 ha = __float2bfloat16(a);
    __nv_bfloat16 hb = __float2bfloat16(b);
    __nv_bfloat162 h2 = __halves2bfloat162(ha, hb);
    __nv_bfloat162 l2 = __halves2bfloat162(__float2bfloat16(a - __bfloat162float(ha)),
                                           __float2bfloat16(b - __bfloat162float(hb)));
    hi = *reinterpret_cast<uint32_t*>(&h2);
    lo = *reinterpret_cast<uint32_t*>(&l2);
}

// ---------------------------------------------------------------------------
// fp32 -> bf16 hi/lo split (contiguous)
// ---------------------------------------------------------------------------
__global__ void split_kernel(const float* __restrict__ src,
                             __nv_bfloat16* __restrict__ hi,
                             __nv_bfloat16* __restrict__ lo, int n4)
{
    int i = blockIdx.x * blockDim.x + threadIdx.x;
    if (i >= n4) return;
    float4 v = reinterpret_cast<const float4*>(src)[i];
    __nv_bfloat16 h0 = __float2bfloat16(v.x);
    __nv_bfloat16 h1 = __float2bfloat16(v.y);
    __nv_bfloat16 h2 = __float2bfloat16(v.z);
    __nv_bfloat16 h3 = __float2bfloat16(v.w);
    __nv_bfloat16 l0 = __float2bfloat16(v.x - __bfloat162float(h0));
    __nv_bfloat16 l1 = __float2bfloat16(v.y - __bfloat162float(h1));
    __nv_bfloat16 l2 = __float2bfloat16(v.z - __bfloat162float(h2));
    __nv_bfloat16 l3 = __float2bfloat16(v.w - __bfloat162float(h3));
    reinterpret_cast<__nv_bfloat162*>(hi)[2 * i]     = __halves2bfloat162(h0, h1);
    reinterpret_cast<__nv_bfloat162*>(hi)[2 * i + 1] = __halves2bfloat162(h2, h3);
    reinterpret_cast<__nv_bfloat162*>(lo)[2 * i]     = __halves2bfloat162(l0, l1);
    reinterpret_cast<__nv_bfloat162*>(lo)[2 * i + 1] = __halves2bfloat162(l2, l3);
}

// strided source (slice of fused qkv): rows x cols slice at col0, row stride
__global__ void split_strided_kernel(const float* __restrict__ src,
                                     __nv_bfloat16* __restrict__ hi,
                                     __nv_bfloat16* __restrict__ lo,
                                     int rows, int cols, int stride, int col0)
{
    int idx = blockIdx.x * blockDim.x + threadIdx.x;
    int n4 = rows * cols / 4;
    if (idx >= n4) return;
    int cpr = cols / 4;
    int r = idx / cpr, c = idx % cpr;
    float4 v = *reinterpret_cast<const float4*>(src + (size_t)r * stride + col0 + c * 4);
    size_t d2 = ((size_t)r * cols + c * 4) >> 1;
    __nv_bfloat16 h0 = __float2bfloat16(v.x);
    __nv_bfloat16 h1 = __float2bfloat16(v.y);
    __nv_bfloat16 h2 = __float2bfloat16(v.z);
    __nv_bfloat16 h3 = __float2bfloat16(v.w);
    reinterpret_cast<__nv_bfloat162*>(hi)[d2]     = __halves2bfloat162(h0, h1);
    reinterpret_cast<__nv_bfloat162*>(hi)[d2 + 1] = __halves2bfloat162(h2, h3);
    reinterpret_cast<__nv_bfloat162*>(lo)[d2]     = __halves2bfloat162(
        __float2bfloat16(v.x - __bfloat162float(h0)), __float2bfloat16(v.y - __bfloat162float(h1)));
    reinterpret_cast<__nv_bfloat162*>(lo)[d2 + 1] = __halves2bfloat162(
        __float2bfloat16(v.z - __bfloat162float(h2)), __float2bfloat16(v.w - __bfloat162float(h3)));
}

// ---------------------------------------------------------------------------
// RoPE + hi/lo split from strided fused-qkv slice (scale pre-folded for Q)
// ---------------------------------------------------------------------------
__global__ void rope_split_kernel(const float* __restrict__ src,
                                  __nv_bfloat16* __restrict__ hi,
                                  __nv_bfloat16* __restrict__ lo,
                                  int nheads, float scale, int stride, int col0)
{
    int idx = blockIdx.x * blockDim.x + threadIdx.x;
    int total = T_LEN * nheads * (HD / 2);
    if (idx >= total) return;
    int i = idx & 63;
    int h = (idx >> 6) % nheads;
    int t = idx / (64 * nheads);
    float inv = powf(10000.0f, -(float)i / 64.0f);
    float f = (float)t * inv;
    float c = cosf(f), s = sinf(f);
    size_t sbase = (size_t)t * stride + col0 + (size_t)h * HD;
    size_t dbase = (size_t)t * nheads * HD + (size_t)h * HD;
    float x1 = src[sbase + i];
    float x2 = src[sbase + i + 64];
    float y1 = (x1 * c - x2 * s) * scale;
    float y2 = (x1 * s + x2 * c) * scale;
    __nv_bfloat16 h1 = __float2bfloat16(y1);
    __nv_bfloat16 h2 = __float2bfloat16(y2);
    hi[dbase + i]      = h1;
    hi[dbase + i + 64] = h2;
    lo[dbase + i]      = __float2bfloat16(y1 - __bfloat162float(h1));
    lo[dbase + i + 64] = __float2bfloat16(y2 - __bfloat162float(h2));
}

// ---------------------------------------------------------------------------
// bf16x3 tensor-core GEMM: C[M,N] = A[M,K] * B[N,K]^T (fp32 accum)
// CTA 128x128, BK=32, 3-stage cp.async pipeline, 256 threads.
// ---------------------------------------------------------------------------
#define GSTAGE 32768

__global__ __launch_bounds__(256) void gemm_bf16x3(
    const __nv_bfloat16* __restrict__ Ah, const __nv_bfloat16* __restrict__ Al,
    const __nv_bfloat16* __restrict__ Bh, const __nv_bfloat16* __restrict__ Bl,
    float* __restrict__ C, int M, int N, int K)
{
    extern __shared__ char smem[];
    const int tid  = threadIdx.x;
    const int lane = tid & 31;
    const int warp = tid >> 5;
    const int wm   = warp >> 2;
    const int wn   = warp & 3;

    const __nv_bfloat16* Abh = Ah + (size_t)blockIdx.y * 128 * K;
    const __nv_bfloat16* Abl = Al + (size_t)blockIdx.y * 128 * K;
    const __nv_bfloat16* Bbh = Bh + (size_t)blockIdx.x * 128 * K;
    const __nv_bfloat16* Bbl = Bl + (size_t)blockIdx.x * 128 * K;

    const uint32_t smem_base = (uint32_t)__cvta_generic_to_shared(smem);

    float acc[4][4][4];
#pragma unroll
    for (int i = 0; i < 4; ++i)
#pragma unroll
        for (int j = 0; j < 4; ++j)
#pragma unroll
            for (int c = 0; c < 4; ++c) acc[i][j][c] = 0.f;

    auto load_stage = [&](int s, int k0) {
#pragma unroll
        for (int i = 0; i < 8; ++i) {
            const __nv_bfloat16* gb = (i < 2) ? Abh : (i < 4) ? Abl : (i < 6) ? Bbh : Bbl;
            int arr = i >> 1;
            int idx = ((i & 1) << 8) + tid;
            int r = idx >> 2, u = idx & 3;
            uint32_t dst = smem_base + s * GSTAGE + arr * 8192 +
                           (((r << 2) + (u ^ ((r >> 1) & 3))) << 4);
            const void* src = gb + (size_t)r * K + k0 + u * 8;
            asm volatile("cp.async.cg.shared.global [%0], [%1], 16;\n" :: "r"(dst), "l"(src));
        }
        asm volatile("cp.async.commit_group;\n");
    };

    const int KT = K >> 5;
    load_stage(0, 0);
    load_stage(1, 32);

    for (int kt = 0; kt < KT; ++kt) {
        if (kt + 1 < KT) { asm volatile("cp.async.wait_group 1;\n"); }
        else             { asm volatile("cp.async.wait_group 0;\n"); }
        __syncthreads();
        if (kt + 2 < KT) {
            int s = (kt + 2) % 3;
            load_stage(s, (kt + 2) << 5);
        }

        const uint32_t stA_h = smem_base + (kt % 3) * GSTAGE;
        const uint32_t stA_l = stA_h + 8192;
        const uint32_t stB_h = stA_h + 16384;
        const uint32_t stB_l = stA_h + 24576;

#pragma unroll
        for (int kk = 0; kk < 2; ++kk) {
            const int k0 = kk * 16;
            uint32_t ah[4][4], al[4][4], bh[4][2], bl[4][2];
#pragma unroll
            for (int mt = 0; mt < 4; ++mt) {
                int row = wm * 64 + mt * 16 + ((lane >> 3) & 1) * 8 + (lane & 7);
                int u   = (k0 >> 3) + (lane >> 4);
                uint32_t off = ((row << 2) + (u ^ ((row >> 1) & 3))) << 4;
                ldm_x4(ah[mt], stA_h + off);
                ldm_x4(al[mt], stA_l + off);
            }
#pragma unroll
            for (int p = 0; p < 2; ++p) {
                int row = wn * 32 + p * 16 + ((lane >> 4) & 1) * 8 + (lane & 7);
                int u   = (k0 >> 3) + ((lane >> 3) & 1);
                uint32_t off = ((row << 2) + (u ^ ((row >> 1) & 3))) << 4;
                uint32_t t0[4], t1[4];
                ldm_x4(t0, stB_h + off);
                bh[p * 2][0] = t0[0]; bh[p * 2][1] = t0[1];
                bh[p * 2 + 1][0] = t0[2]; bh[p * 2 + 1][1] = t0[3];
                ldm_x4(t1, stB_l + off);
                bl[p * 2][0] = t1[0]; bl[p * 2][1] = t1[1];
                bl[p * 2 + 1][0] = t1[2]; bl[p * 2 + 1][1] = t1[3];
            }
#pragma unroll
            for (int mt = 0; mt < 4; ++mt)
#pragma unroll
                for (int nt = 0; nt < 4; ++nt) {
                    mma_bf16(acc[mt][nt], ah[mt], bh[nt]);
                    mma_bf16(acc[mt][nt], ah[mt], bl[nt]);
                    mma_bf16(acc[mt][nt], al[mt], bh[nt]);
                }
        }
    }

    const int grp = lane >> 2, tig = lane & 3;
#pragma unroll
    for (int mt = 0; mt < 4; ++mt)
#pragma unroll
        for (int nt = 0; nt < 4; ++nt) {
            int r0 = blockIdx.y * 128 + wm * 64 + mt * 16 + grp;
            int c0 = blockIdx.x * 128 + wn * 32 + nt * 8 + tig * 2;
            float2 v0 = make_float2(acc[mt][nt][0], acc[mt][nt][1]);
            float2 v1 = make_float2(acc[mt][nt][2], acc[mt][nt][3]);
            *reinterpret_cast<float2*>(&C[(size_t)r0 * N + c0])       = v0;
            *reinterpret_cast<float2*>(&C[(size_t)(r0 + 8) * N + c0]) = v1;
        }
}

// ---------------------------------------------------------------------------
// Tensor-core flash attention (bf16x3 for QK^T and PV) — R7 winner, unchanged
// ---------------------------------------------------------------------------
#define AT_STAGE 32768

__global__ __launch_bounds__(128) void attn_mma(
    const __nv_bfloat16* __restrict__ Qh, const __nv_bfloat16* __restrict__ Ql,
    const __nv_bfloat16* __restrict__ Kh, const __nv_bfloat16* __restrict__ Kl,
    const __nv_bfloat16* __restrict__ Vh, const __nv_bfloat16* __restrict__ Vl,
    __nv_bfloat16* __restrict__ Oh, __nv_bfloat16* __restrict__ Ol)
{
    extern __shared__ char smem[];
    const uint32_t sb = (uint32_t)__cvta_generic_to_shared(smem);
    const int tid = threadIdx.x, lane = tid & 31, w = tid >> 5;
    const int h = blockIdx.y, g = h >> 2;
    const int qt0 = blockIdx.x * 64;
    const int grp = lane >> 2, tig = lane & 3;
    const int row0 = qt0 + w * 16 + grp;

    uint32_t qfh[8][4], qfl[8][4];
#pragma unroll
    for (int c = 0; c < 8; ++c) {
        int d0 = 16 * c + 2 * tig;
        size_t b0 = ((size_t)row0 * QH + h) * HD;
        size_t b1 = ((size_t)(row0 + 8) * QH + h) * HD;
        qfh[c][0] = *reinterpret_cast<const uint32_t*>(Qh + b0 + d0);
        qfh[c][1] = *reinterpret_cast<const uint32_t*>(Qh + b1 + d0);
        qfh[c][2] = *reinterpret_cast<const uint32_t*>(Qh + b0 + d0 + 8);
        qfh[c][3] = *reinterpret_cast<const uint32_t*>(Qh + b1 + d0 + 8);
        qfl[c][0] = *reinterpret_cast<const uint32_t*>(Ql + b0 + d0);
        qfl[c][1] = *reinterpret_cast<const uint32_t*>(Ql + b1 + d0);
        qfl[c][2] = *reinterpret_cast<const uint32_t*>(Ql + b0 + d0 + 8);
        qfl[c][3] = *reinterpret_cast<const uint32_t*>(Ql + b1 + d0 + 8);
    }

    float o[16][4];
#pragma unroll
    for (int n = 0; n < 16; ++n)
#pragma unroll
        for (int j = 0; j < 4; ++j) o[n][j] = 0.f;
    float m0 = -1e30f, m1 = -1e30f, l0 = 0.f, l1 = 0.f;

    int s_lo = qt0 - WINDOW; if (s_lo < 0) s_lo = 0;
    const int n_tiles = (qt0 + 64 - s_lo) / 32;

    auto load_stage = [&](int st, int s0) {
#pragma unroll
        for (int j = 0; j < 16; ++j) {
            int i = tid + 128 * j;
            int arr = i >> 9;
            int rem = i & 511;
            int r = rem >> 4, u = rem & 15;
            const __nv_bfloat16* gp =
                (arr == 0 ? Kh : arr == 1 ? Kl : arr == 2 ? Vh : Vl) +
                ((size_t)(s0 + r) * KVH + g) * HD + u * 8;
            uint32_t dst = sb + st * AT_STAGE + arr * 8192 + r * 256 + ((u ^ (r & 7)) << 4);
            asm volatile("cp.async.cg.shared.global [%0], [%1], 16;\n" :: "r"(dst), "l"(gp));
        }
        asm volatile("cp.async.commit_group;\n");
    };

    load_stage(0, s_lo);

    for (int tile = 0; tile < n_tiles; ++tile) {
        const int s0 = s_lo + tile * 32;
        if (tile + 1 < n_tiles) {
            load_stage((tile + 1) & 1, s0 + 32);
            asm volatile("cp.async.wait_group 1;\n");
        } else {
            asm volatile("cp.async.wait_group 0;\n");
        }
        __syncthreads();

        const uint32_t st = sb + (tile & 1) * AT_STAGE;

        float S[4][4];
#pragma unroll
        for (int n = 0; n < 4; ++n)
#pragma unroll
            for (int j = 0; j < 4; ++j) S[n][j] = 0.f;

#pragma unroll
        for (int c = 0; c < 8; ++c) {
            uint32_t kh[2][4], kl[2][4];
#pragma unroll
            for (int p = 0; p < 2; ++p) {
                int row = p * 16 + (lane & 7) + 8 * ((lane >> 3) & 1);
                int u   = 2 * c + (lane >> 4);
                uint32_t off = row * 256 + ((u ^ (row & 7)) << 4);
                ldm_x4(kh[p], st + off);
                ldm_x4(kl[p], st + 8192 + off);
            }
#pragma unroll
            for (int n = 0; n < 4; ++n) {
                uint32_t bh[2] = { kh[n >> 1][n & 1], kh[n >> 1][(n & 1) + 2] };
                uint32_t bl[2] = { kl[n >> 1][n & 1], kl[n >> 1][(n & 1) + 2] };
                mma_bf16(S[n], qfh[c], bh);
                mma_bf16(S[n], qfh[c], bl);
                mma_bf16(S[n], qfl[c], bh);
            }
        }

        bool causal_safe = (s0 + 31 <= qt0 + 16 * w);
        bool window_safe = (s0 >= qt0 + 16 * w + 15 - WINDOW);
        if (!(causal_safe && window_safe)) {
#pragma unroll
            for (int n = 0; n < 4; ++n)
#pragma unroll
                for (int j = 0; j < 4; ++j) {
                    int s = s0 + 8 * n + 2 * tig + (j & 1);
                    int t = (j < 2) ? row0 : row0 + 8;
                    bool ok = (s <= t) && (t - s <= WINDOW);
                    if (!ok) S[n][j] = -1e30f;
                }
        }

        float mx0 = -1e30f, mx1 = -1e30f;
#pragma unroll
        for (int n = 0; n < 4; ++n) {
            mx0 = fmaxf(mx0, fmaxf(S[n][0], S[n][1]));
            mx1 = fmaxf(mx1, fmaxf(S[n][2], S[n][3]));
        }
        mx0 = fmaxf(mx0, __shfl_xor_sync(0xffffffffu, mx0, 1));
        mx0 = fmaxf(mx0, __shfl_xor_sync(0xffffffffu, mx0, 2));
        mx1 = fmaxf(mx1, __shfl_xor_sync(0xffffffffu, mx1, 1));
        mx1 = fmaxf(mx1, __shfl_xor_sync(0xffffffffu, mx1, 2));

        float mn0 = fmaxf(m0, mx0), mn1 = fmaxf(m1, mx1);
        float fac0 = __expf(m0 - mn0), fac1 = __expf(m1 - mn1);
        m0 = mn0; m1 = mn1;

        float rs0 = 0.f, rs1 = 0.f;
#pragma unroll
        for (int n = 0; n < 4; ++n) {
            S[n][0] = __expf(S[n][0] - mn0);
            S[n][1] = __expf(S[n][1] - mn0);
            S[n][2] = __expf(S[n][2] - mn1);
            S[n][3] = __expf(S[n][3] - mn1);
            rs0 += S[n][0] + S[n][1];
            rs1 += S[n][2] + S[n][3];
        }
        rs0 += __shfl_xor_sync(0xffffffffu, rs0, 1);
        rs0 += __shfl_xor_sync(0xffffffffu, rs0, 2);
        rs1 += __shfl_xor_sync(0xffffffffu, rs1, 1);
        rs1 += __shfl_xor_sync(0xffffffffu, rs1, 2);
        l0 = l0 * fac0 + rs0;
        l1 = l1 * fac1 + rs1;

#pragma unroll
        for (int n = 0; n < 16; ++n) {
            o[n][0] *= fac0; o[n][1] *= fac0;
            o[n][2] *= fac1; o[n][3] *= fac1;
        }

#pragma unroll
        for (int kc = 0; kc < 2; ++kc) {
            int j0 = 2 * kc, j1 = 2 * kc + 1;
            uint32_t pah[4], pal[4];
            pack_hilo(S[j0][0], S[j0][1], pah[0], pal[0]);
            pack_hilo(S[j0][2], S[j0][3], pah[1], pal[1]);
            pack_hilo(S[j1][0], S[j1][1], pah[2], pal[2]);
            pack_hilo(S[j1][2], S[j1][3], pah[3], pal[3]);
#pragma unroll
            for (int dp = 0; dp < 8; ++dp) {
                int row = kc * 16 + (lane & 7) + 8 * ((lane >> 3) & 1);
                int u   = 2 * dp + (lane >> 4);
                uint32_t off = row * 256 + ((u ^ (row & 7)) << 4);
                uint32_t vh[4], vl[4];
                ldm_x4_t(vh, st + 16384 + off);
                ldm_x4_t(vl, st + 24576 + off);
                uint32_t bh0[2] = { vh[0], vh[1] }, bh1[2] = { vh[2], vh[3] };
                uint32_t bl0[2] = { vl[0], vl[1] }, bl1[2] = { vl[2], vl[3] };
                mma_bf16(o[2 * dp],     pah, bh0);
                mma_bf16(o[2 * dp],     pah, bl0);
                mma_bf16(o[2 * dp],     pal, bh0);
                mma_bf16(o[2 * dp + 1], pah, bh1);
                mma_bf16(o[2 * dp + 1], pah, bl1);
                mma_bf16(o[2 * dp + 1], pal, bh1);
            }
        }
        __syncthreads();
    }

    float inv0 = 1.0f / l0, inv1 = 1.0f / l1;
#pragma unroll
    for (int n = 0; n < 16; ++n) {
        int d = 8 * n + 2 * tig;
        float a0 = o[n][0] * inv0, a1 = o[n][1] * inv0;
        float b0 = o[n][2] * inv1, b1 = o[n][3] * inv1;
        uint32_t h0, lo0, h1, lo1;
        pack_hilo(a0, a1, h0, lo0);
        pack_hilo(b0, b1, h1, lo1);
        size_t p0 = ((size_t)row0 * QH + h) * HD + d;
        size_t p1 = ((size_t)(row0 + 8) * QH + h) * HD + d;
        *reinterpret_cast<uint32_t*>(Oh + p0) = h0;
        *reinterpret_cast<uint32_t*>(Ol + p0) = lo0;
        *reinterpret_cast<uint32_t*>(Oh + p1) = h1;
        *reinterpret_cast<uint32_t*>(Ol + p1) = lo1;
    }
}

// ---------------------------------------------------------------------------
extern "C" void kernel_launch(void* const* d_in, const int* in_sizes, int n_in,
                              void* d_out, int out_size)
{
    const float* x  = (const float*)d_in[0];
    const float* wq = (const float*)d_in[1];
    const float* wk = (const float*)d_in[2];
    const float* wv = (const float*)d_in[3];
    const float* wo = (const float*)d_in[4];
    float* out = (float*)d_out;

    float* qkv;
    cudaGetSymbolAddress((void**)&qkv, g_qkv);

    __nv_bfloat16 *xh, *xl, *wch, *wcl, *woh, *wol;
    __nv_bfloat16 *qh, *ql, *kh, *kl, *vh, *vl, *atth, *attl;
    cudaGetSymbolAddress((void**)&xh,  g_xh);   cudaGetSymbolAddress((void**)&xl,  g_xl);
    cudaGetSymbolAddress((void**)&wch, g_wch);  cudaGetSymbolAddress((void**)&wcl, g_wcl);
    cudaGetSymbolAddress((void**)&woh, g_woh);  cudaGetSymbolAddress((void**)&wol, g_wol);
    cudaGetSymbolAddress((void**)&qh,  g_qh);   cudaGetSymbolAddress((void**)&ql,  g_ql);
    cudaGetSymbolAddress((void**)&kh,  g_kh);   cudaGetSymbolAddress((void**)&kl,  g_kl);
    cudaGetSymbolAddress((void**)&vh,  g_vh);   cudaGetSymbolAddress((void**)&vl,  g_vl);
    cudaGetSymbolAddress((void**)&atth, g_atth); cudaGetSymbolAddress((void**)&attl, g_attl);

    cudaFuncSetAttribute(gemm_bf16x3, cudaFuncAttributeMaxDynamicSharedMemorySize, 3 * GSTAGE);
    cudaFuncSetAttribute(attn_mma,    cudaFuncAttributeMaxDynamicSharedMemorySize, 2 * AT_STAGE);

    // input / weight splits (weights concatenated into wch/wcl rows: wq|wk|wv)
    {
        int n4;
        n4 = T_LEN * HIDDEN / 4;
        split_kernel<<<(n4 + 255) / 256, 256>>>(x, xh, xl, n4);
        n4 = QH * HD * HIDDEN / 4;
        split_kernel<<<(n4 + 255) / 256, 256>>>(wq, wch, wcl, n4);
        n4 = KVH * HD * HIDDEN / 4;
        split_kernel<<<(n4 + 255) / 256, 256>>>(
            wk, wch + (size_t)QH * HD * HIDDEN, wcl + (size_t)QH * HD * HIDDEN, n4);
        split_kernel<<<(n4 + 255) / 256, 256>>>(
            wv, wch + (size_t)(QH + KVH) * HD * HIDDEN, wcl + (size_t)(QH + KVH) * HD * HIDDEN, n4);
        n4 = HIDDEN * QH * HD / 4;
        split_kernel<<<(n4 + 255) / 256, 256>>>(wo, woh, wol, n4);
    }

    // fused QKV projection: C[T, 3072]
    gemm_bf16x3<<<dim3(NC / 128, T_LEN / 128), 256, 3 * GSTAGE>>>(
        xh, xl, wch, wcl, qkv, T_LEN, NC, HIDDEN);

    // RoPE + split (scale folded into Q), V split — all from fused buffer
    {
        const float scale = 0.08838834764831845f;  // 1/sqrt(128)
        int totq = T_LEN * QH * (HD / 2);
        rope_split_kernel<<<(totq + 255) / 256, 256>>>(qkv, qh, ql, QH, scale, NC, 0);
        int totk = T_LEN * KVH * (HD / 2);
        rope_split_kernel<<<(totk + 255) / 256, 256>>>(qkv, kh, kl, KVH, 1.0f, NC, QH * HD);
        int n4 = T_LEN * KVH * HD / 4;
        split_strided_kernel<<<(n4 + 255) / 256, 256>>>(
            qkv, vh, vl, T_LEN, KVH * HD, NC, (QH + KVH) * HD);
    }

    // tensor-core attention -> writes hi/lo bf16 directly
    attn_mma<<<dim3(T_LEN / 64, QH), 128, 2 * AT_STAGE>>>(
        qh, ql, kh, kl, vh, vl, atth, attl);

    // output projection
    gemm_bf16x3<<<dim3(HIDDEN / 128, T_LEN / 128), 256, 3 * GSTAGE>>>(
        atth, attl, woh, wol, out, T_LEN, HIDDEN, QH * HD);
}

// round 14
// speedup vs baseline: 4.1924x; 1.0306x over previous
#include <cuda_runtime.h>
#include <cuda_bf16.h>
#include <math.h>
#include <stdint.h>

#define T_LEN  4096
#define HIDDEN 2048
#define QH     16
#define KVH    4
#define HD     128
#define WINDOW 512
#define NC     3072   // fused QKV output width: 2048 + 512 + 512

// ---------------- device scratch (no cudaMalloc allowed) -------------------
__device__ float g_qkv[(size_t)T_LEN * NC];

__device__ __nv_bfloat16 g_xh[(size_t)T_LEN * HIDDEN];
__device__ __nv_bfloat16 g_xl[(size_t)T_LEN * HIDDEN];
__device__ __nv_bfloat16 g_wch[(size_t)NC * HIDDEN];     // concat wq|wk|wv hi
__device__ __nv_bfloat16 g_wcl[(size_t)NC * HIDDEN];     // concat wq|wk|wv lo
__device__ __nv_bfloat16 g_woh[(size_t)HIDDEN * QH * HD];
__device__ __nv_bfloat16 g_wol[(size_t)HIDDEN * QH * HD];

__device__ __nv_bfloat16 g_qh[(size_t)T_LEN * QH * HD];
__device__ __nv_bfloat16 g_ql[(size_t)T_LEN * QH * HD];
__device__ __nv_bfloat16 g_kh[(size_t)T_LEN * KVH * HD];
__device__ __nv_bfloat16 g_kl[(size_t)T_LEN * KVH * HD];
__device__ __nv_bfloat16 g_vh[(size_t)T_LEN * KVH * HD];
__device__ __nv_bfloat16 g_vl[(size_t)T_LEN * KVH * HD];
__device__ __nv_bfloat16 g_atth[(size_t)T_LEN * QH * HD];
__device__ __nv_bfloat16 g_attl[(size_t)T_LEN * QH * HD];

// ---------------------------------------------------------------------------
// helpers
// ---------------------------------------------------------------------------
__device__ __forceinline__ void ldm_x4(uint32_t* r, uint32_t addr)
{
    asm volatile("ldmatrix.sync.aligned.m8n8.x4.shared.b16 {%0,%1,%2,%3}, [%4];\n"
        : "=r"(r[0]), "=r"(r[1]), "=r"(r[2]), "=r"(r[3]) : "r"(addr));
}
__device__ __forceinline__ void ldm_x4_t(uint32_t* r, uint32_t addr)
{
    asm volatile("ldmatrix.sync.aligned.m8n8.x4.trans.shared.b16 {%0,%1,%2,%3}, [%4];\n"
        : "=r"(r[0]), "=r"(r[1]), "=r"(r[2]), "=r"(r[3]) : "r"(addr));
}
__device__ __forceinline__ void mma_bf16(float* d, const uint32_t* a, const uint32_t* b)
{
    asm volatile(
        "mma.sync.aligned.m16n8k16.row.col.f32.bf16.bf16.f32 "
        "{%0,%1,%2,%3}, {%4,%5,%6,%7}, {%8,%9}, {%0,%1,%2,%3};\n"
        : "+f"(d[0]), "+f"(d[1]), "+f"(d[2]), "+f"(d[3])
        : "r"(a[0]), "r"(a[1]), "r"(a[2]), "r"(a[3]), "r"(b[0]), "r"(b[1]));
}
__device__ __forceinline__ void pack_hilo(float a, float b, uint32_t& hi, uint32_t& lo)
{
    __nv_bfloat16 ha = __float2bfloat16(a);
    __nv_bfloat16 hb = __float2bfloat16(b);
    __nv_bfloat162 h2 = __halves2bfloat162(ha, hb);
    __nv_bfloat162 l2 = __halves2bfloat162(__float2bfloat16(a - __bfloat162float(ha)),
                                           __float2bfloat16(b - __bfloat162float(hb)));
    hi = *reinterpret_cast<uint32_t*>(&h2);
    lo = *reinterpret_cast<uint32_t*>(&l2);
}
__device__ __forceinline__ void split_store(float4 v, __nv_bfloat16* hi,
                                            __nv_bfloat16* lo, size_t d2)
{
    __nv_bfloat16 h0 = __float2bfloat16(v.x);
    __nv_bfloat16 h1 = __float2bfloat16(v.y);
    __nv_bfloat16 h2 = __float2bfloat16(v.z);
    __nv_bfloat16 h3 = __float2bfloat16(v.w);
    reinterpret_cast<__nv_bfloat162*>(hi)[d2]     = __halves2bfloat162(h0, h1);
    reinterpret_cast<__nv_bfloat162*>(hi)[d2 + 1] = __halves2bfloat162(h2, h3);
    reinterpret_cast<__nv_bfloat162*>(lo)[d2]     = __halves2bfloat162(
        __float2bfloat16(v.x - __bfloat162float(h0)),
        __float2bfloat16(v.y - __bfloat162float(h1)));
    reinterpret_cast<__nv_bfloat162*>(lo)[d2 + 1] = __halves2bfloat162(
        __float2bfloat16(v.z - __bfloat162float(h2)),
        __float2bfloat16(v.w - __bfloat162float(h3)));
}

// ---------------------------------------------------------------------------
// fp32 -> bf16 hi/lo split (contiguous)
// ---------------------------------------------------------------------------
__global__ void split_kernel(const float* __restrict__ src,
                             __nv_bfloat16* __restrict__ hi,
                             __nv_bfloat16* __restrict__ lo, int n4)
{
    int i = blockIdx.x * blockDim.x + threadIdx.x;
    if (i >= n4) return;
    float4 v = reinterpret_cast<const float4*>(src)[i];
    split_store(v, hi, lo, (size_t)2 * i);
}

// fused split of wq|wk|wv into the concatenated wch/wcl
__global__ void split_w3_kernel(const float* __restrict__ wq,
                                const float* __restrict__ wk,
                                const float* __restrict__ wv,
                                __nv_bfloat16* __restrict__ hi,
                                __nv_bfloat16* __restrict__ lo)
{
    const int n4q = QH * HD * HIDDEN / 4;
    const int n4k = KVH * HD * HIDDEN / 4;
    const int n4t = NC * HIDDEN / 4;
    int i = blockIdx.x * blockDim.x + threadIdx.x;
    if (i >= n4t) return;
    const float* src;
    int j;
    if (i < n4q)            { src = wq; j = i; }
    else if (i < n4q + n4k) { src = wk; j = i - n4q; }
    else                    { src = wv; j = i - n4q - n4k; }
    float4 v = reinterpret_cast<const float4*>(src)[j];
    split_store(v, hi, lo, (size_t)2 * i);
}

// strided source (slice of fused qkv)
__global__ void split_strided_kernel(const float* __restrict__ src,
                                     __nv_bfloat16* __restrict__ hi,
                                     __nv_bfloat16* __restrict__ lo,
                                     int rows, int cols, int stride, int col0)
{
    int idx = blockIdx.x * blockDim.x + threadIdx.x;
    int n4 = rows * cols / 4;
    if (idx >= n4) return;
    int cpr = cols / 4;
    int r = idx / cpr, c = idx % cpr;
    float4 v = *reinterpret_cast<const float4*>(src + (size_t)r * stride + col0 + c * 4);
    split_store(v, hi, lo, ((size_t)r * cols + c * 4) >> 1);
}

// ---------------------------------------------------------------------------
// Fused RoPE + hi/lo split for BOTH q and k slices of the fused qkv buffer.
// Q gets 1/sqrt(HD) pre-folded.
// ---------------------------------------------------------------------------
__global__ void rope_qk_kernel(const float* __restrict__ qkv,
                               __nv_bfloat16* __restrict__ qh, __nv_bfloat16* __restrict__ ql,
                               __nv_bfloat16* __restrict__ kh, __nv_bfloat16* __restrict__ kl)
{
    const int NH = QH + KVH;   // 20
    int idx = blockIdx.x * blockDim.x + threadIdx.x;
    int total = T_LEN * NH * (HD / 2);
    if (idx >= total) return;
    int i  = idx & 63;
    int hh = (idx >> 6) % NH;
    int t  = idx / (64 * NH);
    float inv = powf(10000.0f, -(float)i / 64.0f);
    float f = (float)t * inv;
    float c = cosf(f), s = sinf(f);
    bool isq = (hh < QH);
    int h = isq ? hh : hh - QH;
    float scale = isq ? 0.08838834764831845f : 1.0f;
    size_t sbase = (size_t)t * NC + (isq ? 0 : QH * HD) + (size_t)h * HD;
    __nv_bfloat16* hi = isq ? qh : kh;
    __nv_bfloat16* lo = isq ? ql : kl;
    size_t dbase = (size_t)t * (isq ? QH : KVH) * HD + (size_t)h * HD;
    float x1 = qkv[sbase + i];
    float x2 = qkv[sbase + i + 64];
    float y1 = (x1 * c - x2 * s) * scale;
    float y2 = (x1 * s + x2 * c) * scale;
    __nv_bfloat16 h1 = __float2bfloat16(y1);
    __nv_bfloat16 h2 = __float2bfloat16(y2);
    hi[dbase + i]      = h1;
    hi[dbase + i + 64] = h2;
    lo[dbase + i]      = __float2bfloat16(y1 - __bfloat162float(h1));
    lo[dbase + i + 64] = __float2bfloat16(y2 - __bfloat162float(h2));
}

// ---------------------------------------------------------------------------
// bf16x3 tensor-core GEMM: C[M,N] = A[M,K] * B[N,K]^T (fp32 accum)
// CTA 128x128, BK=32, 3-stage cp.async, 256 threads, 2 CTAs/SM target.
// A-fragments processed in two mt-halves to keep regs <= 128.
// ---------------------------------------------------------------------------
#define GSTAGE 32768

__global__ __launch_bounds__(256, 2) void gemm_bf16x3(
    const __nv_bfloat16* __restrict__ Ah, const __nv_bfloat16* __restrict__ Al,
    const __nv_bfloat16* __restrict__ Bh, const __nv_bfloat16* __restrict__ Bl,
    float* __restrict__ C, int M, int N, int K)
{
    extern __shared__ char smem[];
    const int tid  = threadIdx.x;
    const int lane = tid & 31;
    const int warp = tid >> 5;
    const int wm   = warp >> 2;
    const int wn   = warp & 3;

    const __nv_bfloat16* Abh = Ah + (size_t)blockIdx.y * 128 * K;
    const __nv_bfloat16* Abl = Al + (size_t)blockIdx.y * 128 * K;
    const __nv_bfloat16* Bbh = Bh + (size_t)blockIdx.x * 128 * K;
    const __nv_bfloat16* Bbl = Bl + (size_t)blockIdx.x * 128 * K;

    const uint32_t smem_base = (uint32_t)__cvta_generic_to_shared(smem);

    float acc[4][4][4];
#pragma unroll
    for (int i = 0; i < 4; ++i)
#pragma unroll
        for (int j = 0; j < 4; ++j)
#pragma unroll
            for (int c = 0; c < 4; ++c) acc[i][j][c] = 0.f;

    auto load_stage = [&](int s, int k0) {
#pragma unroll
        for (int i = 0; i < 8; ++i) {
            const __nv_bfloat16* gb = (i < 2) ? Abh : (i < 4) ? Abl : (i < 6) ? Bbh : Bbl;
            int arr = i >> 1;
            int idx = ((i & 1) << 8) + tid;
            int r = idx >> 2, u = idx & 3;
            uint32_t dst = smem_base + s * GSTAGE + arr * 8192 +
                           (((r << 2) + (u ^ ((r >> 1) & 3))) << 4);
            const void* src = gb + (size_t)r * K + k0 + u * 8;
            asm volatile("cp.async.cg.shared.global [%0], [%1], 16;\n" :: "r"(dst), "l"(src));
        }
        asm volatile("cp.async.commit_group;\n");
    };

    const int KT = K >> 5;
    load_stage(0, 0);
    load_stage(1, 32);

    for (int kt = 0; kt < KT; ++kt) {
        if (kt + 1 < KT) { asm volatile("cp.async.wait_group 1;\n"); }
        else             { asm volatile("cp.async.wait_group 0;\n"); }
        __syncthreads();
        if (kt + 2 < KT) {
            int s = (kt + 2) % 3;
            load_stage(s, (kt + 2) << 5);
        }

        const uint32_t stA_h = smem_base + (kt % 3) * GSTAGE;
        const uint32_t stA_l = stA_h + 8192;
        const uint32_t stB_h = stA_h + 16384;
        const uint32_t stB_l = stA_h + 24576;

#pragma unroll
        for (int kk = 0; kk < 2; ++kk) {
            const int k0 = kk * 16;
            uint32_t bh[4][2], bl[4][2];
#pragma unroll
            for (int p = 0; p < 2; ++p) {
                int row = wn * 32 + p * 16 + ((lane >> 4) & 1) * 8 + (lane & 7);
                int u   = (k0 >> 3) + ((lane >> 3) & 1);
                uint32_t off = ((row << 2) + (u ^ ((row >> 1) & 3))) << 4;
                uint32_t t0[4], t1[4];
                ldm_x4(t0, stB_h + off);
                bh[p * 2][0] = t0[0]; bh[p * 2][1] = t0[1];
                bh[p * 2 + 1][0] = t0[2]; bh[p * 2 + 1][1] = t0[3];
                ldm_x4(t1, stB_l + off);
                bl[p * 2][0] = t1[0]; bl[p * 2][1] = t1[1];
                bl[p * 2 + 1][0] = t1[2]; bl[p * 2 + 1][1] = t1[3];
            }
#pragma unroll
            for (int mth = 0; mth < 2; ++mth) {
                uint32_t ah[2][4], al[2][4];
#pragma unroll
                for (int mt2 = 0; mt2 < 2; ++mt2) {
                    int mt = mth * 2 + mt2;
                    int row = wm * 64 + mt * 16 + ((lane >> 3) & 1) * 8 + (lane & 7);
                    int u   = (k0 >> 3) + (lane >> 4);
                    uint32_t off = ((row << 2) + (u ^ ((row >> 1) & 3))) << 4;
                    ldm_x4(ah[mt2], stA_h + off);
                    ldm_x4(al[mt2], stA_l + off);
                }
#pragma unroll
                for (int mt2 = 0; mt2 < 2; ++mt2)
#pragma unroll
                    for (int nt = 0; nt < 4; ++nt) {
                        float* d = acc[mth * 2 + mt2][nt];
                        mma_bf16(d, ah[mt2], bh[nt]);
                        mma_bf16(d, ah[mt2], bl[nt]);
                        mma_bf16(d, al[mt2], bh[nt]);
                    }
            }
        }
    }

    const int grp = lane >> 2, tig = lane & 3;
#pragma unroll
    for (int mt = 0; mt < 4; ++mt)
#pragma unroll
        for (int nt = 0; nt < 4; ++nt) {
            int r0 = blockIdx.y * 128 + wm * 64 + mt * 16 + grp;
            int c0 = blockIdx.x * 128 + wn * 32 + nt * 8 + tig * 2;
            float2 v0 = make_float2(acc[mt][nt][0], acc[mt][nt][1]);
            float2 v1 = make_float2(acc[mt][nt][2], acc[mt][nt][3]);
            *reinterpret_cast<float2*>(&C[(size_t)r0 * N + c0])       = v0;
            *reinterpret_cast<float2*>(&C[(size_t)(r0 + 8) * N + c0]) = v1;
        }
}

// ---------------------------------------------------------------------------
// Tensor-core flash attention (bf16x3 for QK^T and PV) — unchanged
// ---------------------------------------------------------------------------
#define AT_STAGE 32768

__global__ __launch_bounds__(128) void attn_mma(
    const __nv_bfloat16* __restrict__ Qh, const __nv_bfloat16* __restrict__ Ql,
    const __nv_bfloat16* __restrict__ Kh, const __nv_bfloat16* __restrict__ Kl,
    const __nv_bfloat16* __restrict__ Vh, const __nv_bfloat16* __restrict__ Vl,
    __nv_bfloat16* __restrict__ Oh, __nv_bfloat16* __restrict__ Ol)
{
    extern __shared__ char smem[];
    const uint32_t sb = (uint32_t)__cvta_generic_to_shared(smem);
    const int tid = threadIdx.x, lane = tid & 31, w = tid >> 5;
    const int h = blockIdx.y, g = h >> 2;
    const int qt0 = blockIdx.x * 64;
    const int grp = lane >> 2, tig = lane & 3;
    const int row0 = qt0 + w * 16 + grp;

    uint32_t qfh[8][4], qfl[8][4];
#pragma unroll
    for (int c = 0; c < 8; ++c) {
        int d0 = 16 * c + 2 * tig;
        size_t b0 = ((size_t)row0 * QH + h) * HD;
        size_t b1 = ((size_t)(row0 + 8) * QH + h) * HD;
        qfh[c][0] = *reinterpret_cast<const uint32_t*>(Qh + b0 + d0);
        qfh[c][1] = *reinterpret_cast<const uint32_t*>(Qh + b1 + d0);
        qfh[c][2] = *reinterpret_cast<const uint32_t*>(Qh + b0 + d0 + 8);
        qfh[c][3] = *reinterpret_cast<const uint32_t*>(Qh + b1 + d0 + 8);
        qfl[c][0] = *reinterpret_cast<const uint32_t*>(Ql + b0 + d0);
        qfl[c][1] = *reinterpret_cast<const uint32_t*>(Ql + b1 + d0);
        qfl[c][2] = *reinterpret_cast<const uint32_t*>(Ql + b0 + d0 + 8);
        qfl[c][3] = *reinterpret_cast<const uint32_t*>(Ql + b1 + d0 + 8);
    }

    float o[16][4];
#pragma unroll
    for (int n = 0; n < 16; ++n)
#pragma unroll
        for (int j = 0; j < 4; ++j) o[n][j] = 0.f;
    float m0 = -1e30f, m1 = -1e30f, l0 = 0.f, l1 = 0.f;

    int s_lo = qt0 - WINDOW; if (s_lo < 0) s_lo = 0;
    const int n_tiles = (qt0 + 64 - s_lo) / 32;

    auto load_stage = [&](int st, int s0) {
#pragma unroll
        for (int j = 0; j < 16; ++j) {
            int i = tid + 128 * j;
            int arr = i >> 9;
            int rem = i & 511;
            int r = rem >> 4, u = rem & 15;
            const __nv_bfloat16* gp =
                (arr == 0 ? Kh : arr == 1 ? Kl : arr == 2 ? Vh : Vl) +
                ((size_t)(s0 + r) * KVH + g) * HD + u * 8;
            uint32_t dst = sb + st * AT_STAGE + arr * 8192 + r * 256 + ((u ^ (r & 7)) << 4);
            asm volatile("cp.async.cg.shared.global [%0], [%1], 16;\n" :: "r"(dst), "l"(gp));
        }
        asm volatile("cp.async.commit_group;\n");
    };

    load_stage(0, s_lo);

    for (int tile = 0; tile < n_tiles; ++tile) {
        const int s0 = s_lo + tile * 32;
        if (tile + 1 < n_tiles) {
            load_stage((tile + 1) & 1, s0 + 32);
            asm volatile("cp.async.wait_group 1;\n");
        } else {
            asm volatile("cp.async.wait_group 0;\n");
        }
        __syncthreads();

        const uint32_t st = sb + (tile & 1) * AT_STAGE;

        float S[4][4];
#pragma unroll
        for (int n = 0; n < 4; ++n)
#pragma unroll
            for (int j = 0; j < 4; ++j) S[n][j] = 0.f;

#pragma unroll
        for (int c = 0; c < 8; ++c) {
            uint32_t kh[2][4], kl[2][4];
#pragma unroll
            for (int p = 0; p < 2; ++p) {
                int row = p * 16 + (lane & 7) + 8 * ((lane >> 3) & 1);
                int u   = 2 * c + (lane >> 4);
                uint32_t off = row * 256 + ((u ^ (row & 7)) << 4);
                ldm_x4(kh[p], st + off);
                ldm_x4(kl[p], st + 8192 + off);
            }
#pragma unroll
            for (int n = 0; n < 4; ++n) {
                uint32_t bh[2] = { kh[n >> 1][n & 1], kh[n >> 1][(n & 1) + 2] };
                uint32_t bl[2] = { kl[n >> 1][n & 1], kl[n >> 1][(n & 1) + 2] };
                mma_bf16(S[n], qfh[c], bh);
                mma_bf16(S[n], qfh[c], bl);
                mma_bf16(S[n], qfl[c], bh);
            }
        }

        bool causal_safe = (s0 + 31 <= qt0 + 16 * w);
        bool window_safe = (s0 >= qt0 + 16 * w + 15 - WINDOW);
        if (!(causal_safe && window_safe)) {
#pragma unroll
            for (int n = 0; n < 4; ++n)
#pragma unroll
                for (int j = 0; j < 4; ++j) {
                    int s = s0 + 8 * n + 2 * tig + (j & 1);
                    int t = (j < 2) ? row0 : row0 + 8;
                    bool ok = (s <= t) && (t - s <= WINDOW);
                    if (!ok) S[n][j] = -1e30f;
                }
        }

        float mx0 = -1e30f, mx1 = -1e30f;
#pragma unroll
        for (int n = 0; n < 4; ++n) {
            mx0 = fmaxf(mx0, fmaxf(S[n][0], S[n][1]));
            mx1 = fmaxf(mx1, fmaxf(S[n][2], S[n][3]));
        }
        mx0 = fmaxf(mx0, __shfl_xor_sync(0xffffffffu, mx0, 1));
        mx0 = fmaxf(mx0, __shfl_xor_sync(0xffffffffu, mx0, 2));
        mx1 = fmaxf(mx1, __shfl_xor_sync(0xffffffffu, mx1, 1));
        mx1 = fmaxf(mx1, __shfl_xor_sync(0xffffffffu, mx1, 2));

        float mn0 = fmaxf(m0, mx0), mn1 = fmaxf(m1, mx1);
        float fac0 = __expf(m0 - mn0), fac1 = __expf(m1 - mn1);
        m0 = mn0; m1 = mn1;

        float rs0 = 0.f, rs1 = 0.f;
#pragma unroll
        for (int n = 0; n < 4; ++n) {
            S[n][0] = __expf(S[n][0] - mn0);
            S[n][1] = __expf(S[n][1] - mn0);
            S[n][2] = __expf(S[n][2] - mn1);
            S[n][3] = __expf(S[n][3] - mn1);
            rs0 += S[n][0] + S[n][1];
            rs1 += S[n][2] + S[n][3];
        }
        rs0 += __shfl_xor_sync(0xffffffffu, rs0, 1);
        rs0 += __shfl_xor_sync(0xffffffffu, rs0, 2);
        rs1 += __shfl_xor_sync(0xffffffffu, rs1, 1);
        rs1 += __shfl_xor_sync(0xffffffffu, rs1, 2);
        l0 = l0 * fac0 + rs0;
        l1 = l1 * fac1 + rs1;

#pragma unroll
        for (int n = 0; n < 16; ++n) {
            o[n][0] *= fac0; o[n][1] *= fac0;
            o[n][2] *= fac1; o[n][3] *= fac1;
        }

#pragma unroll
        for (int kc = 0; kc < 2; ++kc) {
            int j0 = 2 * kc, j1 = 2 * kc + 1;
            uint32_t pah[4], pal[4];
            pack_hilo(S[j0][0], S[j0][1], pah[0], pal[0]);
            pack_hilo(S[j0][2], S[j0][3], pah[1], pal[1]);
            pack_hilo(S[j1][0], S[j1][1], pah[2], pal[2]);
            pack_hilo(S[j1][2], S[j1][3], pah[3], pal[3]);
#pragma unroll
            for (int dp = 0; dp < 8; ++dp) {
                int row = kc * 16 + (lane & 7) + 8 * ((lane >> 3) & 1);
                int u   = 2 * dp + (lane >> 4);
                uint32_t off = row * 256 + ((u ^ (row & 7)) << 4);
                uint32_t vh[4], vl[4];
                ldm_x4_t(vh, st + 16384 + off);
                ldm_x4_t(vl, st + 24576 + off);
                uint32_t bh0[2] = { vh[0], vh[1] }, bh1[2] = { vh[2], vh[3] };
                uint32_t bl0[2] = { vl[0], vl[1] }, bl1[2] = { vl[2], vl[3] };
                mma_bf16(o[2 * dp],     pah, bh0);
                mma_bf16(o[2 * dp],     pah, bl0);
                mma_bf16(o[2 * dp],     pal, bh0);
                mma_bf16(o[2 * dp + 1], pah, bh1);
                mma_bf16(o[2 * dp + 1], pah, bl1);
                mma_bf16(o[2 * dp + 1], pal, bh1);
            }
        }
        __syncthreads();
    }

    float inv0 = 1.0f / l0, inv1 = 1.0f / l1;
#pragma unroll
    for (int n = 0; n < 16; ++n) {
        int d = 8 * n + 2 * tig;
        float a0 = o[n][0] * inv0, a1 = o[n][1] * inv0;
        float b0 = o[n][2] * inv1, b1 = o[n][3] * inv1;
        uint32_t h0, lo0, h1, lo1;
        pack_hilo(a0, a1, h0, lo0);
        pack_hilo(b0, b1, h1, lo1);
        size_t p0 = ((size_t)row0 * QH + h) * HD + d;
        size_t p1 = ((size_t)(row0 + 8) * QH + h) * HD + d;
        *reinterpret_cast<uint32_t*>(Oh + p0) = h0;
        *reinterpret_cast<uint32_t*>(Ol + p0) = lo0;
        *reinterpret_cast<uint32_t*>(Oh + p1) = h1;
        *reinterpret_cast<uint32_t*>(Ol + p1) = lo1;
    }
}

// ---------------------------------------------------------------------------
extern "C" void kernel_launch(void* const* d_in, const int* in_sizes, int n_in,
                              void* d_out, int out_size)
{
    const float* x  = (const float*)d_in[0];
    const float* wq = (const float*)d_in[1];
    const float* wk = (const float*)d_in[2];
    const float* wv = (const float*)d_in[3];
    const float* wo = (const float*)d_in[4];
    float* out = (float*)d_out;

    float* qkv;
    cudaGetSymbolAddress((void**)&qkv, g_qkv);

    __nv_bfloat16 *xh, *xl, *wch, *wcl, *woh, *wol;
    __nv_bfloat16 *qh, *ql, *kh, *kl, *vh, *vl, *atth, *attl;
    cudaGetSymbolAddress((void**)&xh,  g_xh);   cudaGetSymbolAddress((void**)&xl,  g_xl);
    cudaGetSymbolAddress((void**)&wch, g_wch);  cudaGetSymbolAddress((void**)&wcl, g_wcl);
    cudaGetSymbolAddress((void**)&woh, g_woh);  cudaGetSymbolAddress((void**)&wol, g_wol);
    cudaGetSymbolAddress((void**)&qh,  g_qh);   cudaGetSymbolAddress((void**)&ql,  g_ql);
    cudaGetSymbolAddress((void**)&kh,  g_kh);   cudaGetSymbolAddress((void**)&kl,  g_kl);
    cudaGetSymbolAddress((void**)&vh,  g_vh);   cudaGetSymbolAddress((void**)&vl,  g_vl);
    cudaGetSymbolAddress((void**)&atth, g_atth); cudaGetSymbolAddress((void**)&attl, g_attl);

    cudaFuncSetAttribute(gemm_bf16x3, cudaFuncAttributeMaxDynamicSharedMemorySize, 3 * GSTAGE);
    cudaFuncSetAttribute(attn_mma,    cudaFuncAttributeMaxDynamicSharedMemorySize, 2 * AT_STAGE);

    // #1: split x
    {
        int n4 = T_LEN * HIDDEN / 4;
        split_kernel<<<(n4 + 255) / 256, 256>>>(x, xh, xl, n4);
    }
    // #2: fused split of wq|wk|wv into wch/wcl
    {
        int n4 = NC * HIDDEN / 4;
        split_w3_kernel<<<(n4 + 255) / 256, 256>>>(wq, wk, wv, wch, wcl);
    }
    // #3: split wo
    {
        int n4 = HIDDEN * QH * HD / 4;
        split_kernel<<<(n4 + 255) / 256, 256>>>(wo, woh, wol, n4);
    }
    // #4: fused QKV projection (this launch position gets profiled by ncu)
    gemm_bf16x3<<<dim3(NC / 128, T_LEN / 128), 256, 3 * GSTAGE>>>(
        xh, xl, wch, wcl, qkv, T_LEN, NC, HIDDEN);
    // #5: fused RoPE+split for q and k
    {
        int tot = T_LEN * (QH + KVH) * (HD / 2);
        rope_qk_kernel<<<(tot + 255) / 256, 256>>>(qkv, qh, ql, kh, kl);
    }
    // #6: V split from fused buffer
    {
        int n4 = T_LEN * KVH * HD / 4;
        split_strided_kernel<<<(n4 + 255) / 256, 256>>>(
            qkv, vh, vl, T_LEN, KVH * HD, NC, (QH + KVH) * HD);
    }
    // #7: tensor-core attention -> writes hi/lo bf16 directly
    attn_mma<<<dim3(T_LEN / 64, QH), 128, 2 * AT_STAGE>>>(
        qh, ql, kh, kl, vh, vl, atth, attl);
    // #8: output projection
    gemm_bf16x3<<<dim3(HIDDEN / 128, T_LEN / 128), 256, 3 * GSTAGE>>>(
        atth, attl, woh, wol, out, T_LEN, HIDDEN, QH * HD);
}